// round 4
// baseline (speedup 1.0000x reference)
#include <cuda_runtime.h>
#include <math.h>

using ull = unsigned long long;

constexpr int B_   = 32;
constexpr int C_   = 64;
constexpr int L_   = 512;
constexpr int S_   = 4;
constexpr int NP_  = 125;
constexpr int D_   = 128;
constexpr int INNER_ = 256;
constexpr int CP_  = 1024;        // C*P
constexpr int M_   = B_ * NP_;    // 4000
constexpr int CF_  = 6144;        // C*F
constexpr int DNP_ = 16000;       // D*NP
constexpr int KS_  = 25;          // split-K for final GEMM
constexpr float EPS_ = 1e-5f;

// -------- device scratch (no allocation allowed) --------
__device__ float g_h[M_ * D_];          // hidden (B,NP,D) contiguous == flat layout
__device__ float g_scale[M_];           // rmsnorm scale per row (for NEXT consumer)
__device__ float g_a[M_ * INNER_];      // in-proj a   (also reused as s*b after scan)
__device__ float g_bv[M_ * INNER_];     // in-proj b
__device__ float g_u[M_ * INNER_];      // silu(conv(a))
__device__ float g_part[KS_ * B_ * CF_];// split-K partials
__device__ float g_pe[NP_ * D_];        // accurate sincos PE table

// -------- f32x2 helpers (Blackwell packed fp32) --------
__device__ __forceinline__ ull pk2(float lo, float hi) {
    ull r; asm("mov.b64 %0,{%1,%2};" : "=l"(r) : "f"(lo), "f"(hi)); return r;
}
__device__ __forceinline__ ull f2fma(ull a, ull b, ull c) {
    ull d; asm("fma.rn.f32x2 %0,%1,%2,%3;" : "=l"(d) : "l"(a), "l"(b), "l"(c)); return d;
}
__device__ __forceinline__ float2 upk2(ull v) {
    float2 r; asm("mov.b64 {%0,%1},%2;" : "=f"(r.x), "=f"(r.y) : "l"(v)); return r;
}

// =====================================================================
// Kernel 0: accurate sincos PE table (fp64 sin/cos of the fp32-rounded
// argument, matching the reference's fp32 pos*div then accurate sin).
// =====================================================================
__global__ __launch_bounds__(128) void k_pe() {
    int idx = blockIdx.x * 128 + threadIdx.x;   // 125*128 = 16000 exact
    int kq = idx >> 7, col = idx & 127;
    int ii = col >> 1;
    float targ = (-9.210340371976184f) * (float)ii * (1.0f / 64.0f);
    float divf = (float)exp((double)targ);
    float ang = (float)kq * divf;               // fp32 rounding like reference
    double a = (double)ang;
    g_pe[idx] = (float)((col & 1) ? cos(a) : sin(a));
}

// =====================================================================
// Kernel 1: patch embed GEMM (4000x128 = xp(4000x1024) @ pe_W^T) + bias
//           + sincos PE, epilogue computes rmsnorm scale for layer 0.
// =====================================================================
__global__ __launch_bounds__(256) void k_embed(const float* __restrict__ x,
                                               const float* __restrict__ peW,
                                               const float* __restrict__ peb) {
    __shared__ __align__(16) float As[32][64];
    __shared__ __align__(16) float Ws[64][128];  // XOR-swizzled, k-major
    const int t = threadIdx.x, rg = t >> 5, cg = t & 31, rg4 = rg * 4;
    const int rowbase = blockIdx.x * 32;

    ull acc[4][2];
#pragma unroll
    for (int i = 0; i < 4; i++) { acc[i][0] = 0ull; acc[i][1] = 0ull; }

    for (int kc = 0; kc < 16; kc++) {
        // A tile: As[row][kk] = x[b, c, k*4+p],  gk = kc*64+kk -> (c,p)
        for (int idx = t; idx < 32 * 64; idx += 256) {
            int row = idx >> 6, kk = idx & 63;
            int gk = kc * 64 + kk, c = gk >> 4, p = gk & 15;
            int grow = rowbase + row;
            int bb = grow / 125, kq = grow - bb * 125;
            As[row][kk] = x[(bb * C_ + c) * L_ + kq * S_ + p];
        }
        // W tile (transposed to k-major with XOR swizzle on 16B units)
        for (int idx = t; idx < 64 * 128; idx += 256) {
            int d = idx >> 6, kk = idx & 63;
            float v = peW[d * CP_ + kc * 64 + kk];
            int up = (d >> 2) ^ (kk & 31);
            Ws[kk][(up << 2) | (d & 3)] = v;
        }
        __syncthreads();
#pragma unroll
        for (int kk = 0; kk < 64; kk++) {
            ulonglong2 wv = *reinterpret_cast<const ulonglong2*>(
                &Ws[kk][(cg ^ (kk & 31)) << 2]);
#pragma unroll
            for (int i = 0; i < 4; i++) {
                float a = As[rg4 + i][kk];
                ull ap = pk2(a, a);
                acc[i][0] = f2fma(ap, wv.x, acc[i][0]);
                acc[i][1] = f2fma(ap, wv.y, acc[i][1]);
            }
        }
        __syncthreads();
    }

#pragma unroll
    for (int i = 0; i < 4; i++) {
        int grow = rowbase + rg4 + i;
        int bb = grow / 125, kq = grow - bb * 125;
        float2 v0 = upk2(acc[i][0]), v1 = upk2(acc[i][1]);
        float vals[4] = {v0.x, v0.y, v1.x, v1.y};
        float4 pe4 = *reinterpret_cast<const float4*>(&g_pe[kq * D_ + (cg << 2)]);
        float4 pb4 = *reinterpret_cast<const float4*>(&peb[cg << 2]);
        float4 outv;
        float ssq = 0.f;
#pragma unroll
        for (int j = 0; j < 4; j++) {
            float v = vals[j] + ((const float*)&pb4)[j] + ((const float*)&pe4)[j];
            ((float*)&outv)[j] = v;
            ssq += v * v;
        }
        *reinterpret_cast<float4*>(&g_h[grow * D_ + (cg << 2)]) = outv;
#pragma unroll
        for (int off = 16; off > 0; off >>= 1)
            ssq += __shfl_xor_sync(0xffffffffu, ssq, off);
        if (cg == 0) g_scale[grow] = rsqrtf(ssq * (1.0f / 128.0f) + EPS_);
    }
}

// =====================================================================
// Kernel 2: fused rmsnorm + in-projections a,b  (M=4000, K=128, N=2x256)
// grid.y selects 128-col chunk: 0,1 -> a ; 2,3 -> b. norm_w folded into W,
// row scale folded into epilogue.
// =====================================================================
__global__ __launch_bounds__(256) void k_inproj(const float* __restrict__ aW,
                                                const float* __restrict__ bW,
                                                const float* __restrict__ nw) {
    __shared__ __align__(16) float As[32][128];
    __shared__ __align__(16) float Ws[32][128];
    __shared__ float scl[32];
    const int t = threadIdx.x, rg = t >> 5, cg = t & 31, rg4 = rg * 4;
    const int rowbase = blockIdx.x * 32;
    const int ny = blockIdx.y;
    const float* W = ((ny < 2) ? aW : bW) + (ny & 1) * 128 * D_;
    float* out = (ny < 2) ? g_a : g_bv;
    const int colbase = (ny & 1) * 128;

    for (int idx = t; idx < 32 * 128; idx += 256) {
        int row = idx >> 7, kk = idx & 127;
        As[row][kk] = g_h[(rowbase + row) * D_ + kk];
    }
    if (t < 32) scl[t] = g_scale[rowbase + t];

    ull acc[4][2];
#pragma unroll
    for (int i = 0; i < 4; i++) { acc[i][0] = 0ull; acc[i][1] = 0ull; }

    for (int kc = 0; kc < 4; kc++) {
        for (int idx = t; idx < 32 * 128; idx += 256) {
            int n = idx >> 5, kk = idx & 31;
            int gk = kc * 32 + kk;
            float v = W[n * D_ + gk] * nw[gk];
            int up = (n >> 2) ^ kk;
            Ws[kk][(up << 2) | (n & 3)] = v;
        }
        __syncthreads();
#pragma unroll
        for (int kk = 0; kk < 32; kk++) {
            ulonglong2 wv = *reinterpret_cast<const ulonglong2*>(&Ws[kk][(cg ^ kk) << 2]);
#pragma unroll
            for (int i = 0; i < 4; i++) {
                float a = As[rg4 + i][kc * 32 + kk];
                ull ap = pk2(a, a);
                acc[i][0] = f2fma(ap, wv.x, acc[i][0]);
                acc[i][1] = f2fma(ap, wv.y, acc[i][1]);
            }
        }
        __syncthreads();
    }
#pragma unroll
    for (int i = 0; i < 4; i++) {
        int grow = rowbase + rg4 + i;
        float s = scl[rg4 + i];
        float2 v0 = upk2(acc[i][0]), v1 = upk2(acc[i][1]);
        float4 o4 = make_float4(v0.x * s, v0.y * s, v1.x * s, v1.y * s);
        *reinterpret_cast<float4*>(&out[grow * INNER_ + colbase + (cg << 2)]) = o4;
    }
}

// =====================================================================
// Kernel 3a: depthwise conv (K=5, pad=2 over k) + bias + silu -> g_u
// one thread per (b,k,i); fully parallel (keeps silu off the scan chain)
// =====================================================================
__global__ __launch_bounds__(256) void k_conv(const float* __restrict__ cw,
                                              const float* __restrict__ cb) {
    const int bk = blockIdx.x;              // b*125 + k
    const int i = threadIdx.x;
    const int k = bk % 125;
    const int base = bk * INNER_ + i;
    const float* w = cw + i * 5;
    float acc = cb[i];
    if (k >= 2)   acc = fmaf(w[0], g_a[base - 2 * INNER_], acc);
    if (k >= 1)   acc = fmaf(w[1], g_a[base - INNER_], acc);
    acc = fmaf(w[2], g_a[base], acc);
    if (k <= 123) acc = fmaf(w[3], g_a[base + INNER_], acc);
    if (k <= 122) acc = fmaf(w[4], g_a[base + 2 * INNER_], acc);
    g_u[base] = acc / (1.f + __expf(-acc));
}

// =====================================================================
// Kernel 3b: selective scan over k, times b-gate -> g_a (reused buffer)
// one thread per (b, channel); serial chain is a single FFMA per step
// =====================================================================
__global__ __launch_bounds__(256) void k_scan(const float* __restrict__ al,
                                              const float* __restrict__ be,
                                              const float* __restrict__ ga,
                                              const float* __restrict__ de) {
    const int g = blockIdx.x * 256 + threadIdx.x;   // 8192 total
    const int b = g >> 8, i = g & 255;
    const float siga = 1.f / (1.f + __expf(-al[i]));
    const float bb = be[i], gg = ga[i], dd = de[i];
    int idx = b * 125 * INNER_ + i;
    float s = 0.f;
#pragma unroll 5
    for (int k = 0; k < 125; k++, idx += INNER_) {
        float u = g_u[idx];
        float bv = g_bv[idx];
        s = fmaf(siga, s, bb * u);
        float y = fmaf(gg, s, dd * u);
        g_a[idx] = y * bv;
    }
}

// =====================================================================
// Kernel 4: out-projection + DOUBLED residual (reference does
// h <- h + (h + y) = 2h + y ; rmsnorm consumers make it scale-invariant,
// but the direction must match). Epilogue computes next rmsnorm scale.
// =====================================================================
__global__ __launch_bounds__(256) void k_outproj(const float* __restrict__ oW) {
    __shared__ __align__(16) float As[32][256];
    __shared__ __align__(16) float Ws[32][128];
    const int t = threadIdx.x, rg = t >> 5, cg = t & 31, rg4 = rg * 4;
    const int rowbase = blockIdx.x * 32;

    for (int idx = t; idx < 32 * 256; idx += 256) {
        int row = idx >> 8, kk = idx & 255;
        As[row][kk] = g_a[(rowbase + row) * INNER_ + kk];
    }

    ull acc[4][2];
#pragma unroll
    for (int i = 0; i < 4; i++) { acc[i][0] = 0ull; acc[i][1] = 0ull; }

    for (int kc = 0; kc < 8; kc++) {
        for (int idx = t; idx < 32 * 128; idx += 256) {
            int n = idx >> 5, kk = idx & 31;
            float v = oW[n * INNER_ + kc * 32 + kk];
            int up = (n >> 2) ^ kk;
            Ws[kk][(up << 2) | (n & 3)] = v;
        }
        __syncthreads();
#pragma unroll
        for (int kk = 0; kk < 32; kk++) {
            ulonglong2 wv = *reinterpret_cast<const ulonglong2*>(&Ws[kk][(cg ^ kk) << 2]);
#pragma unroll
            for (int i = 0; i < 4; i++) {
                float a = As[rg4 + i][kc * 32 + kk];
                ull ap = pk2(a, a);
                acc[i][0] = f2fma(ap, wv.x, acc[i][0]);
                acc[i][1] = f2fma(ap, wv.y, acc[i][1]);
            }
        }
        __syncthreads();
    }
#pragma unroll
    for (int i = 0; i < 4; i++) {
        int grow = rowbase + rg4 + i;
        float4 hv = *reinterpret_cast<const float4*>(&g_h[grow * D_ + (cg << 2)]);
        float2 v0 = upk2(acc[i][0]), v1 = upk2(acc[i][1]);
        // h_new = 2*h + y  (matches reference h + _block(h) with _block = x + y)
        float4 nv = make_float4(2.f * hv.x + v0.x, 2.f * hv.y + v0.y,
                                2.f * hv.z + v1.x, 2.f * hv.w + v1.y);
        *reinterpret_cast<float4*>(&g_h[grow * D_ + (cg << 2)]) = nv;
        float ssq = nv.x * nv.x + nv.y * nv.y + nv.z * nv.z + nv.w * nv.w;
#pragma unroll
        for (int off = 16; off > 0; off >>= 1)
            ssq += __shfl_xor_sync(0xffffffffu, ssq, off);
        if (cg == 0) g_scale[grow] = rsqrtf(ssq * (1.0f / 128.0f) + EPS_);
    }
}

// =====================================================================
// Kernel 5: final big GEMM  y[32,6144] = flat[32,16000] @ out_W^T,
// final rmsnorm folded into the flat-tile load. Split-K=25 -> partials.
// Each block: 64 output cols x all 32 batches, f32x2 packed FMA.
// =====================================================================
__global__ __launch_bounds__(256) void k_final(const float* __restrict__ outW,
                                               const float* __restrict__ nfw) {
    __shared__ __align__(16) float fs[32][128];
    const int t = threadIdx.x;
    const int ol = t >> 2, gq = t & 3;
    const int o = blockIdx.x * 64 + ol;
    const int ks = blockIdx.y;
    const int jbase = ks * (DNP_ / KS_);   // 640 per split
    const float* wrow = outW + (size_t)o * DNP_ + jbase;

    ull acc[32];
#pragma unroll
    for (int b = 0; b < 32; b++) acc[b] = 0ull;

    for (int chunk = 0; chunk < 5; chunk++) {
        int j0 = jbase + chunk * 128;
        int kq = j0 >> 7;                  // each 128-chunk == one position k
        for (int idx4 = t; idx4 < 32 * 32; idx4 += 256) {
            int b = idx4 >> 5, q = idx4 & 31;
            float sc = g_scale[b * 125 + kq];
            float4 hv = *reinterpret_cast<const float4*>(&g_h[b * DNP_ + j0 + (q << 2)]);
            float4 nv = *reinterpret_cast<const float4*>(&nfw[(q << 2)]);
            float4 r = make_float4(hv.x * sc * nv.x, hv.y * sc * nv.y,
                                   hv.z * sc * nv.z, hv.w * sc * nv.w);
            *reinterpret_cast<float4*>(&fs[b][q << 2]) = r;
        }
        __syncthreads();
#pragma unroll
        for (int u = 0; u < 8; u++) {
            int jl = (gq << 2) + (u << 4);
            ulonglong2 wv = *reinterpret_cast<const ulonglong2*>(&wrow[chunk * 128 + jl]);
#pragma unroll
            for (int b = 0; b < 32; b++) {
                ulonglong2 fv = *reinterpret_cast<const ulonglong2*>(&fs[b][jl]);
                acc[b] = f2fma(fv.x, wv.x, acc[b]);
                acc[b] = f2fma(fv.y, wv.y, acc[b]);
            }
        }
        __syncthreads();
    }
#pragma unroll
    for (int b = 0; b < 32; b++) {
        float2 v2 = upk2(acc[b]);
        float v = v2.x + v2.y;
        v += __shfl_down_sync(0xffffffffu, v, 2, 4);
        v += __shfl_down_sync(0xffffffffu, v, 1, 4);
        if (gq == 0) g_part[(ks * B_ + b) * CF_ + o] = v;
    }
}

// Kernel 6: reduce split-K partials + bias -> d_out (deterministic, no atomics)
__global__ __launch_bounds__(256) void k_reduce(const float* __restrict__ outb,
                                                float* __restrict__ out) {
    int idx = blockIdx.x * 256 + threadIdx.x;   // 196608 = 768*256 exact
    int b = idx / CF_, o = idx - b * CF_;
    float v = outb[o];
#pragma unroll
    for (int s = 0; s < KS_; s++) v += g_part[(s * B_ + b) * CF_ + o];
    out[idx] = v;
}

// =====================================================================
extern "C" void kernel_launch(void* const* d_in, const int* in_sizes, int n_in,
                              void* d_out, int out_size) {
    const float* x     = (const float*)d_in[0];
    const float* peW   = (const float*)d_in[1];
    const float* peb   = (const float*)d_in[2];
    const float* normw = (const float*)d_in[3];
    const float* ipaW  = (const float*)d_in[4];
    const float* ipbW  = (const float*)d_in[5];
    const float* convW = (const float*)d_in[6];
    const float* convb = (const float*)d_in[7];
    const float* alp   = (const float*)d_in[8];
    const float* bet   = (const float*)d_in[9];
    const float* gam   = (const float*)d_in[10];
    const float* del   = (const float*)d_in[11];
    const float* opW   = (const float*)d_in[12];
    const float* normf = (const float*)d_in[13];
    const float* outW  = (const float*)d_in[14];
    const float* outb  = (const float*)d_in[15];
    float* out = (float*)d_out;

    k_pe<<<NP_, 128>>>();
    k_embed<<<M_ / 32, 256>>>(x, peW, peb);
    for (int l = 0; l < 4; l++) {
        k_inproj<<<dim3(M_ / 32, 4), 256>>>(ipaW + l * INNER_ * D_,
                                            ipbW + l * INNER_ * D_,
                                            normw + l * D_);
        k_conv<<<M_, 256>>>(convW + l * INNER_ * 5, convb + l * INNER_);
        k_scan<<<(B_ * INNER_) / 256, 256>>>(alp + l * INNER_, bet + l * INNER_,
                                             gam + l * INNER_, del + l * INNER_);
        k_outproj<<<M_ / 32, 256>>>(opW + l * D_ * INNER_);
    }
    k_final<<<dim3(CF_ / 64, KS_), 256>>>(outW, normf);
    k_reduce<<<(B_ * CF_) / 256, 256>>>(outb, out);
}

// round 5
// speedup vs baseline: 1.5350x; 1.5350x over previous
#include <cuda_runtime.h>
#include <math.h>

using ull = unsigned long long;

constexpr int B_   = 32;
constexpr int C_   = 64;
constexpr int L_   = 512;
constexpr int S_   = 4;
constexpr int NP_  = 125;
constexpr int D_   = 128;
constexpr int INNER_ = 256;
constexpr int CP_  = 1024;        // C*P
constexpr int M_   = B_ * NP_;    // 4000
constexpr int CF_  = 6144;        // C*F
constexpr int DNP_ = 16000;       // D*NP
constexpr int KS_  = 25;          // split-K for final GEMM (640 k each)
constexpr float EPS_ = 1e-5f;

// -------- device scratch (no allocation allowed) --------
__device__ float g_h[M_ * D_];          // hidden (B,NP,D) contiguous == flat layout
__device__ float g_scale[M_];           // rmsnorm scale per row (for NEXT consumer)
__device__ float g_a[M_ * INNER_];      // in-proj a (overwritten with gated scan out)
__device__ float g_bv[M_ * INNER_];     // in-proj b
__device__ float g_u[M_ * INNER_];      // reused: normalized flat for k_final
__device__ float g_part[KS_ * B_ * CF_];// split-K partials
__device__ float g_pe[NP_ * D_];        // accurate sincos PE table

// -------- f32x2 helpers (Blackwell packed fp32) --------
__device__ __forceinline__ ull pk2(float lo, float hi) {
    ull r; asm("mov.b64 %0,{%1,%2};" : "=l"(r) : "f"(lo), "f"(hi)); return r;
}
__device__ __forceinline__ ull f2fma(ull a, ull b, ull c) {
    ull d; asm("fma.rn.f32x2 %0,%1,%2,%3;" : "=l"(d) : "l"(a), "l"(b), "l"(c)); return d;
}
__device__ __forceinline__ float2 upk2(ull v) {
    float2 r; asm("mov.b64 {%0,%1},%2;" : "=f"(r.x), "=f"(r.y) : "l"(v)); return r;
}
__device__ __forceinline__ void cp16(unsigned s, const float* g) {
    asm volatile("cp.async.cg.shared.global [%0],[%1],16;" :: "r"(s), "l"(g));
}
__device__ __forceinline__ void cp_commit() { asm volatile("cp.async.commit_group;"); }
__device__ __forceinline__ void cp_waitall() { asm volatile("cp.async.wait_group 0;" ::: "memory"); }

// =====================================================================
// Kernel 0: accurate sincos PE table
// =====================================================================
__global__ __launch_bounds__(128) void k_pe() {
    int idx = blockIdx.x * 128 + threadIdx.x;   // 125*128 = 16000 exact
    int kq = idx >> 7, col = idx & 127;
    int ii = col >> 1;
    float targ = (-9.210340371976184f) * (float)ii * (1.0f / 64.0f);
    float divf = (float)exp((double)targ);
    float ang = (float)kq * divf;               // fp32 rounding like reference
    double a = (double)ang;
    g_pe[idx] = (float)((col & 1) ? cos(a) : sin(a));
}

// =====================================================================
// Kernel 1: patch embed GEMM + bias + sincos PE; epilogue -> rmsnorm scale
// =====================================================================
__global__ __launch_bounds__(256) void k_embed(const float* __restrict__ x,
                                               const float* __restrict__ peW,
                                               const float* __restrict__ peb) {
    __shared__ __align__(16) float As[32][64];
    __shared__ __align__(16) float Ws[64][128];  // XOR-swizzled, k-major
    const int t = threadIdx.x, rg = t >> 5, cg = t & 31, rg4 = rg * 4;
    const int rowbase = blockIdx.x * 32;

    ull acc[4][2];
#pragma unroll
    for (int i = 0; i < 4; i++) { acc[i][0] = 0ull; acc[i][1] = 0ull; }

    for (int kc = 0; kc < 16; kc++) {
        for (int idx = t; idx < 32 * 64; idx += 256) {
            int row = idx >> 6, kk = idx & 63;
            int gk = kc * 64 + kk, c = gk >> 4, p = gk & 15;
            int grow = rowbase + row;
            int bb = grow / 125, kq = grow - bb * 125;
            As[row][kk] = x[(bb * C_ + c) * L_ + kq * S_ + p];
        }
        for (int idx = t; idx < 64 * 128; idx += 256) {
            int d = idx >> 6, kk = idx & 63;
            float v = peW[d * CP_ + kc * 64 + kk];
            int up = (d >> 2) ^ (kk & 31);
            Ws[kk][(up << 2) | (d & 3)] = v;
        }
        __syncthreads();
#pragma unroll
        for (int kk = 0; kk < 64; kk++) {
            ulonglong2 wv = *reinterpret_cast<const ulonglong2*>(
                &Ws[kk][(cg ^ (kk & 31)) << 2]);
#pragma unroll
            for (int i = 0; i < 4; i++) {
                float a = As[rg4 + i][kk];
                ull ap = pk2(a, a);
                acc[i][0] = f2fma(ap, wv.x, acc[i][0]);
                acc[i][1] = f2fma(ap, wv.y, acc[i][1]);
            }
        }
        __syncthreads();
    }

#pragma unroll
    for (int i = 0; i < 4; i++) {
        int grow = rowbase + rg4 + i;
        int bb = grow / 125, kq = grow - bb * 125;
        float2 v0 = upk2(acc[i][0]), v1 = upk2(acc[i][1]);
        float vals[4] = {v0.x, v0.y, v1.x, v1.y};
        float4 pe4 = *reinterpret_cast<const float4*>(&g_pe[kq * D_ + (cg << 2)]);
        float4 pb4 = *reinterpret_cast<const float4*>(&peb[cg << 2]);
        float4 outv;
        float ssq = 0.f;
#pragma unroll
        for (int j = 0; j < 4; j++) {
            float v = vals[j] + ((const float*)&pb4)[j] + ((const float*)&pe4)[j];
            ((float*)&outv)[j] = v;
            ssq += v * v;
        }
        *reinterpret_cast<float4*>(&g_h[grow * D_ + (cg << 2)]) = outv;
#pragma unroll
        for (int off = 16; off > 0; off >>= 1)
            ssq += __shfl_xor_sync(0xffffffffu, ssq, off);
        if (cg == 0) g_scale[grow] = rsqrtf(ssq * (1.0f / 128.0f) + EPS_);
    }
}

// =====================================================================
// Kernel 2: fused rmsnorm + in-projections a,b  (M=4000, K=128, N=2x256)
// =====================================================================
__global__ __launch_bounds__(256) void k_inproj(const float* __restrict__ aW,
                                                const float* __restrict__ bW,
                                                const float* __restrict__ nw) {
    __shared__ __align__(16) float As[32][128];
    __shared__ __align__(16) float Ws[32][128];
    __shared__ float scl[32];
    const int t = threadIdx.x, rg = t >> 5, cg = t & 31, rg4 = rg * 4;
    const int rowbase = blockIdx.x * 32;
    const int ny = blockIdx.y;
    const float* W = ((ny < 2) ? aW : bW) + (ny & 1) * 128 * D_;
    float* out = (ny < 2) ? g_a : g_bv;
    const int colbase = (ny & 1) * 128;

    for (int idx = t; idx < 32 * 128; idx += 256) {
        int row = idx >> 7, kk = idx & 127;
        As[row][kk] = g_h[(rowbase + row) * D_ + kk];
    }
    if (t < 32) scl[t] = g_scale[rowbase + t];

    ull acc[4][2];
#pragma unroll
    for (int i = 0; i < 4; i++) { acc[i][0] = 0ull; acc[i][1] = 0ull; }

    for (int kc = 0; kc < 4; kc++) {
        for (int idx = t; idx < 32 * 128; idx += 256) {
            int n = idx >> 5, kk = idx & 31;
            int gk = kc * 32 + kk;
            float v = W[n * D_ + gk] * nw[gk];
            int up = (n >> 2) ^ kk;
            Ws[kk][(up << 2) | (n & 3)] = v;
        }
        __syncthreads();
#pragma unroll
        for (int kk = 0; kk < 32; kk++) {
            ulonglong2 wv = *reinterpret_cast<const ulonglong2*>(&Ws[kk][(cg ^ kk) << 2]);
#pragma unroll
            for (int i = 0; i < 4; i++) {
                float a = As[rg4 + i][kc * 32 + kk];
                ull ap = pk2(a, a);
                acc[i][0] = f2fma(ap, wv.x, acc[i][0]);
                acc[i][1] = f2fma(ap, wv.y, acc[i][1]);
            }
        }
        __syncthreads();
    }
#pragma unroll
    for (int i = 0; i < 4; i++) {
        int grow = rowbase + rg4 + i;
        float s = scl[rg4 + i];
        float2 v0 = upk2(acc[i][0]), v1 = upk2(acc[i][1]);
        float4 o4 = make_float4(v0.x * s, v0.y * s, v1.x * s, v1.y * s);
        *reinterpret_cast<float4*>(&out[grow * INNER_ + colbase + (cg << 2)]) = o4;
    }
}

// =====================================================================
// Kernel 3: MERGED depthwise conv + silu + selective scan + b-gate.
// One thread per (b, channel); rolling conv window in registers; loads
// batched in groups of 5 (MLP~10). Writes gated output back to g_a
// (write at k trails all reads of positions >= k within the group).
// =====================================================================
__global__ __launch_bounds__(64) void k_convscan(const float* __restrict__ cw,
                                                 const float* __restrict__ cb,
                                                 const float* __restrict__ al,
                                                 const float* __restrict__ be,
                                                 const float* __restrict__ ga,
                                                 const float* __restrict__ de) {
    const int g = blockIdx.x * 64 + threadIdx.x;    // 8192 total
    const int b = g >> 8, i = g & 255;
    const float* w = cw + i * 5;
    const float w0 = w[0], w1 = w[1], w2 = w[2], w3 = w[3], w4 = w[4];
    const float bias = cb[i];
    const float siga = 1.f / (1.f + __expf(-al[i]));
    const float bb = be[i], gg = ga[i], dd = de[i];
    const int base = b * 125 * INNER_ + i;

    float am2 = 0.f, am1 = 0.f;
    float a0 = g_a[base];
    float ap1 = g_a[base + INNER_];
    float s = 0.f;

    for (int grp = 0; grp < 25; grp++) {
        const int k0 = grp * 5;
        float na[5], nb[5];
#pragma unroll
        for (int q = 0; q < 5; q++) {
            int kk = k0 + q + 2;
            na[q] = (kk <= 124) ? g_a[base + kk * INNER_] : 0.f;
            nb[q] = g_bv[base + (k0 + q) * INNER_];
        }
#pragma unroll
        for (int q = 0; q < 5; q++) {
            float acc = bias;
            acc = fmaf(w0, am2, acc);
            acc = fmaf(w1, am1, acc);
            acc = fmaf(w2, a0, acc);
            acc = fmaf(w3, ap1, acc);
            acc = fmaf(w4, na[q], acc);
            float u = acc / (1.f + __expf(-acc));
            s = fmaf(siga, s, bb * u);
            float y = fmaf(gg, s, dd * u);
            g_a[base + (k0 + q) * INNER_] = y * nb[q];
            am2 = am1; am1 = a0; a0 = ap1; ap1 = na[q];
        }
    }
}

// =====================================================================
// Kernel 4: out-projection + DOUBLED residual (h <- 2h + y); epilogue
// computes next rmsnorm scale.
// =====================================================================
__global__ __launch_bounds__(256) void k_outproj(const float* __restrict__ oW) {
    __shared__ __align__(16) float As[32][256];
    __shared__ __align__(16) float Ws[32][128];
    const int t = threadIdx.x, rg = t >> 5, cg = t & 31, rg4 = rg * 4;
    const int rowbase = blockIdx.x * 32;

    for (int idx = t; idx < 32 * 256; idx += 256) {
        int row = idx >> 8, kk = idx & 255;
        As[row][kk] = g_a[(rowbase + row) * INNER_ + kk];
    }

    ull acc[4][2];
#pragma unroll
    for (int i = 0; i < 4; i++) { acc[i][0] = 0ull; acc[i][1] = 0ull; }

    for (int kc = 0; kc < 8; kc++) {
        for (int idx = t; idx < 32 * 128; idx += 256) {
            int n = idx >> 5, kk = idx & 31;
            float v = oW[n * INNER_ + kc * 32 + kk];
            int up = (n >> 2) ^ kk;
            Ws[kk][(up << 2) | (n & 3)] = v;
        }
        __syncthreads();
#pragma unroll
        for (int kk = 0; kk < 32; kk++) {
            ulonglong2 wv = *reinterpret_cast<const ulonglong2*>(&Ws[kk][(cg ^ kk) << 2]);
#pragma unroll
            for (int i = 0; i < 4; i++) {
                float a = As[rg4 + i][kc * 32 + kk];
                ull ap = pk2(a, a);
                acc[i][0] = f2fma(ap, wv.x, acc[i][0]);
                acc[i][1] = f2fma(ap, wv.y, acc[i][1]);
            }
        }
        __syncthreads();
    }
#pragma unroll
    for (int i = 0; i < 4; i++) {
        int grow = rowbase + rg4 + i;
        float4 hv = *reinterpret_cast<const float4*>(&g_h[grow * D_ + (cg << 2)]);
        float2 v0 = upk2(acc[i][0]), v1 = upk2(acc[i][1]);
        float4 nv = make_float4(2.f * hv.x + v0.x, 2.f * hv.y + v0.y,
                                2.f * hv.z + v1.x, 2.f * hv.w + v1.y);
        *reinterpret_cast<float4*>(&g_h[grow * D_ + (cg << 2)]) = nv;
        float ssq = nv.x * nv.x + nv.y * nv.y + nv.z * nv.z + nv.w * nv.w;
#pragma unroll
        for (int off = 16; off > 0; off >>= 1)
            ssq += __shfl_xor_sync(0xffffffffu, ssq, off);
        if (cg == 0) g_scale[grow] = rsqrtf(ssq * (1.0f / 128.0f) + EPS_);
    }
}

// =====================================================================
// Kernel 5a: materialize normalized flat activations once:
// g_u[b*16000+j] = g_h[..] * scale(row) * normf_w[j%128]
// =====================================================================
__global__ __launch_bounds__(256) void k_normflat(const float* __restrict__ nfw) {
    int idx = blockIdx.x * 256 + threadIdx.x;   // 128000 float4 groups (grid 500)
    float sc = g_scale[idx >> 5];               // (idx*4)>>7
    int j4 = idx << 2;
    float4 h = *reinterpret_cast<const float4*>(&g_h[j4]);
    float4 nv = *reinterpret_cast<const float4*>(&nfw[j4 & 127]);
    float4 r = make_float4(h.x * sc * nv.x, h.y * sc * nv.y,
                           h.z * sc * nv.z, h.w * sc * nv.w);
    *reinterpret_cast<float4*>(&g_u[j4]) = r;
}

// =====================================================================
// Kernel 5b: final GEMM  y[32,6144] = flat[32,16000] @ out_W^T
// Block: 64 outputs x 32 batches, split-K (640 k per split).
// Weights cp.async double-buffered in 32-k subtiles; flat staged per
// 128-k chunk. Thread tile 2o x 4b, f32x2 packed FMA (j-pair packing).
// =====================================================================
__global__ __launch_bounds__(256) void k_final(const float* __restrict__ outW) {
    // ws rows: 32 k-floats + 4 pad = 36 floats (9 x 16B, odd -> bank rotate)
    // fs rows: 128 k-floats + 4 pad = 132 floats (33 x 16B, odd)
    __shared__ __align__(16) float ws[2][64][36];
    __shared__ __align__(16) float fs[32][132];

    const int t = threadIdx.x;
    const int o_grp = t >> 3;          // 0..31  -> 2 output rows each
    const int b_lane = t & 7;          // 0..7   -> 4 batches each (stride 8)
    const int obase = blockIdx.x * 64;
    const int ks = blockIdx.y;
    const int jbase = ks * 640;

    const unsigned ws_base = (unsigned)__cvta_generic_to_shared(&ws[0][0][0]);
    const unsigned fs_base = (unsigned)__cvta_generic_to_shared(&fs[0][0]);

    ull acc[2][4];
#pragma unroll
    for (int i = 0; i < 2; i++)
#pragma unroll
        for (int j = 0; j < 4; j++) acc[i][j] = 0ull;

    // ---- staging lambdas (inlined manually) ----
    // ws subtile s (32 k): 64 rows x 128B ; 512 16B-chunks / 256 thr = 2 each
    auto stage_ws = [&](int buf, int s) {
#pragma unroll
        for (int q = 0; q < 2; q++) {
            int c = t * 2 + q;
            int o = c >> 3, kc = c & 7;
            const float* gsrc = outW + (size_t)(obase + o) * DNP_ + jbase + s * 32 + kc * 4;
            unsigned dst = ws_base + (((buf * 64 + o) * 36 + kc * 4) << 2);
            cp16(dst, gsrc);
        }
    };
    // fs chunk ch (128 k): 32 rows x 512B ; 1024 chunks / 256 thr = 4 each
    auto stage_fs = [&](int ch) {
#pragma unroll
        for (int q = 0; q < 4; q++) {
            int c = t + 256 * q;
            int b = c >> 5, kc = c & 31;
            const float* gsrc = g_u + b * DNP_ + jbase + ch * 128 + kc * 4;
            unsigned dst = fs_base + ((b * 132 + kc * 4) << 2);
            cp16(dst, gsrc);
        }
    };

    // prologue
    stage_ws(0, 0);
    stage_fs(0);
    cp_commit();
    cp_waitall();
    __syncthreads();

    for (int s = 0; s < 20; s++) {
        const int buf = s & 1;
        if (s + 1 < 20) { stage_ws(buf ^ 1, s + 1); cp_commit(); }

        const int fb = (s & 3) * 32;
#pragma unroll
        for (int kk = 0; kk < 8; kk++) {
            ulonglong2 wv[2];
#pragma unroll
            for (int i = 0; i < 2; i++)
                wv[i] = *reinterpret_cast<const ulonglong2*>(
                    &ws[buf][o_grp * 2 + i][kk * 4]);
#pragma unroll
            for (int j = 0; j < 4; j++) {
                ulonglong2 fv = *reinterpret_cast<const ulonglong2*>(
                    &fs[b_lane + 8 * j][fb + kk * 4]);
#pragma unroll
                for (int i = 0; i < 2; i++) {
                    acc[i][j] = f2fma(fv.x, wv[i].x, acc[i][j]);
                    acc[i][j] = f2fma(fv.y, wv[i].y, acc[i][j]);
                }
            }
        }

        if ((s & 3) == 3 && s + 1 < 20) {
            __syncthreads();               // all fs consumers done
            stage_fs((s + 1) >> 2);
            cp_commit();
        }
        cp_waitall();
        __syncthreads();
    }

#pragma unroll
    for (int i = 0; i < 2; i++)
#pragma unroll
        for (int j = 0; j < 4; j++) {
            float2 v2 = upk2(acc[i][j]);
            float v = v2.x + v2.y;
            int o = obase + o_grp * 2 + i;
            int b = b_lane + 8 * j;
            g_part[(ks * B_ + b) * CF_ + o] = v;
        }
}

// Kernel 6: reduce split-K partials + bias -> d_out (deterministic)
__global__ __launch_bounds__(256) void k_reduce(const float* __restrict__ outb,
                                                float* __restrict__ out) {
    int idx = blockIdx.x * 256 + threadIdx.x;   // 196608 = 768*256 exact
    int b = idx / CF_, o = idx - b * CF_;
    float v = outb[o];
#pragma unroll
    for (int s = 0; s < KS_; s++) v += g_part[(s * B_ + b) * CF_ + o];
    out[idx] = v;
}

// =====================================================================
extern "C" void kernel_launch(void* const* d_in, const int* in_sizes, int n_in,
                              void* d_out, int out_size) {
    const float* x     = (const float*)d_in[0];
    const float* peW   = (const float*)d_in[1];
    const float* peb   = (const float*)d_in[2];
    const float* normw = (const float*)d_in[3];
    const float* ipaW  = (const float*)d_in[4];
    const float* ipbW  = (const float*)d_in[5];
    const float* convW = (const float*)d_in[6];
    const float* convb = (const float*)d_in[7];
    const float* alp   = (const float*)d_in[8];
    const float* bet   = (const float*)d_in[9];
    const float* gam   = (const float*)d_in[10];
    const float* del   = (const float*)d_in[11];
    const float* opW   = (const float*)d_in[12];
    const float* normf = (const float*)d_in[13];
    const float* outW  = (const float*)d_in[14];
    const float* outb  = (const float*)d_in[15];
    float* out = (float*)d_out;

    k_pe<<<NP_, 128>>>();
    k_embed<<<M_ / 32, 256>>>(x, peW, peb);
    for (int l = 0; l < 4; l++) {
        k_inproj<<<dim3(M_ / 32, 4), 256>>>(ipaW + l * INNER_ * D_,
                                            ipbW + l * INNER_ * D_,
                                            normw + l * D_);
        k_convscan<<<(B_ * INNER_) / 64, 64>>>(convW + l * INNER_ * 5,
                                               convb + l * INNER_,
                                               alp + l * INNER_, bet + l * INNER_,
                                               gam + l * INNER_, del + l * INNER_);
        k_outproj<<<M_ / 32, 256>>>(opW + l * D_ * INNER_);
    }
    k_normflat<<<500, 256>>>(normf);
    k_final<<<dim3(CF_ / 64, KS_), 256>>>(outW);
    k_reduce<<<(B_ * CF_) / 256, 256>>>(outb, out);
}

// round 6
// speedup vs baseline: 1.6675x; 1.0863x over previous
#include <cuda_runtime.h>
#include <math.h>

using ull = unsigned long long;

constexpr int B_   = 32;
constexpr int C_   = 64;
constexpr int L_   = 512;
constexpr int S_   = 4;
constexpr int NP_  = 125;
constexpr int D_   = 128;
constexpr int INNER_ = 256;
constexpr int CP_  = 1024;        // C*P
constexpr int M_   = B_ * NP_;    // 4000
constexpr int CF_  = 6144;        // C*F
constexpr int DNP_ = 16000;       // D*NP
constexpr int KS_  = 25;          // split-K for final GEMM (640 k each)
constexpr float EPS_ = 1e-5f;

// -------- device scratch (no allocation allowed) --------
__device__ float g_h[M_ * D_];          // hidden (B,NP,D) contiguous == flat layout
__device__ float g_scale[M_];           // rmsnorm scale per row (for NEXT consumer)
__device__ float g_a[M_ * INNER_];      // in-proj a
__device__ float g_bv[M_ * INNER_];     // in-proj b
__device__ float g_u[M_ * INNER_];      // gated scan out; later normalized flat
__device__ float g_part[KS_ * B_ * CF_];// split-K partials
__device__ float g_pe[NP_ * D_];        // accurate sincos PE table

// -------- f32x2 helpers (Blackwell packed fp32) --------
__device__ __forceinline__ ull pk2(float lo, float hi) {
    ull r; asm("mov.b64 %0,{%1,%2};" : "=l"(r) : "f"(lo), "f"(hi)); return r;
}
__device__ __forceinline__ ull f2fma(ull a, ull b, ull c) {
    ull d; asm("fma.rn.f32x2 %0,%1,%2,%3;" : "=l"(d) : "l"(a), "l"(b), "l"(c)); return d;
}
__device__ __forceinline__ float2 upk2(ull v) {
    float2 r; asm("mov.b64 {%0,%1},%2;" : "=f"(r.x), "=f"(r.y) : "l"(v)); return r;
}
__device__ __forceinline__ void cp16(unsigned s, const float* g) {
    asm volatile("cp.async.cg.shared.global [%0],[%1],16;" :: "r"(s), "l"(g));
}
__device__ __forceinline__ void cp_commit() { asm volatile("cp.async.commit_group;"); }
__device__ __forceinline__ void cp_waitall() { asm volatile("cp.async.wait_group 0;" ::: "memory"); }

// =====================================================================
// Kernel 0: accurate sincos PE table
// =====================================================================
__global__ __launch_bounds__(128) void k_pe() {
    int idx = blockIdx.x * 128 + threadIdx.x;   // 125*128 = 16000 exact
    int kq = idx >> 7, col = idx & 127;
    int ii = col >> 1;
    float targ = (-9.210340371976184f) * (float)ii * (1.0f / 64.0f);
    float divf = (float)exp((double)targ);
    float ang = (float)kq * divf;               // fp32 rounding like reference
    double a = (double)ang;
    g_pe[idx] = (float)((col & 1) ? cos(a) : sin(a));
}

// =====================================================================
// Kernel 1: patch embed GEMM + bias + sincos PE; epilogue -> rmsnorm scale
// =====================================================================
__global__ __launch_bounds__(256) void k_embed(const float* __restrict__ x,
                                               const float* __restrict__ peW,
                                               const float* __restrict__ peb) {
    __shared__ __align__(16) float As[32][64];
    __shared__ __align__(16) float Ws[64][128];  // XOR-swizzled, k-major
    const int t = threadIdx.x, rg = t >> 5, cg = t & 31, rg4 = rg * 4;
    const int rowbase = blockIdx.x * 32;

    ull acc[4][2];
#pragma unroll
    for (int i = 0; i < 4; i++) { acc[i][0] = 0ull; acc[i][1] = 0ull; }

    for (int kc = 0; kc < 16; kc++) {
        for (int idx = t; idx < 32 * 64; idx += 256) {
            int row = idx >> 6, kk = idx & 63;
            int gk = kc * 64 + kk, c = gk >> 4, p = gk & 15;
            int grow = rowbase + row;
            int bb = grow / 125, kq = grow - bb * 125;
            As[row][kk] = x[(bb * C_ + c) * L_ + kq * S_ + p];
        }
        for (int idx = t; idx < 64 * 128; idx += 256) {
            int d = idx >> 6, kk = idx & 63;
            float v = peW[d * CP_ + kc * 64 + kk];
            int up = (d >> 2) ^ (kk & 31);
            Ws[kk][(up << 2) | (d & 3)] = v;
        }
        __syncthreads();
#pragma unroll
        for (int k4 = 0; k4 < 16; k4++) {
            float4 av4[4];
#pragma unroll
            for (int i = 0; i < 4; i++)
                av4[i] = *reinterpret_cast<const float4*>(&As[rg4 + i][k4 * 4]);
#pragma unroll
            for (int q = 0; q < 4; q++) {
                int kk = k4 * 4 + q;
                ulonglong2 wv = *reinterpret_cast<const ulonglong2*>(
                    &Ws[kk][(cg ^ (kk & 31)) << 2]);
#pragma unroll
                for (int i = 0; i < 4; i++) {
                    float a = ((const float*)&av4[i])[q];
                    ull ap = pk2(a, a);
                    acc[i][0] = f2fma(ap, wv.x, acc[i][0]);
                    acc[i][1] = f2fma(ap, wv.y, acc[i][1]);
                }
            }
        }
        __syncthreads();
    }

#pragma unroll
    for (int i = 0; i < 4; i++) {
        int grow = rowbase + rg4 + i;
        int bb = grow / 125, kq = grow - bb * 125;
        float2 v0 = upk2(acc[i][0]), v1 = upk2(acc[i][1]);
        float vals[4] = {v0.x, v0.y, v1.x, v1.y};
        float4 pe4 = *reinterpret_cast<const float4*>(&g_pe[kq * D_ + (cg << 2)]);
        float4 pb4 = *reinterpret_cast<const float4*>(&peb[cg << 2]);
        float4 outv;
        float ssq = 0.f;
#pragma unroll
        for (int j = 0; j < 4; j++) {
            float v = vals[j] + ((const float*)&pb4)[j] + ((const float*)&pe4)[j];
            ((float*)&outv)[j] = v;
            ssq += v * v;
        }
        *reinterpret_cast<float4*>(&g_h[grow * D_ + (cg << 2)]) = outv;
#pragma unroll
        for (int off = 16; off > 0; off >>= 1)
            ssq += __shfl_xor_sync(0xffffffffu, ssq, off);
        if (cg == 0) g_scale[grow] = rsqrtf(ssq * (1.0f / 128.0f) + EPS_);
    }
}

// =====================================================================
// Kernel 2: fused rmsnorm + in-projections a,b  (M=4000, K=128, N=2x256)
// =====================================================================
__global__ __launch_bounds__(256) void k_inproj(const float* __restrict__ aW,
                                                const float* __restrict__ bW,
                                                const float* __restrict__ nw) {
    __shared__ __align__(16) float As[32][128];
    __shared__ __align__(16) float Ws[32][128];
    __shared__ float scl[32];
    const int t = threadIdx.x, rg = t >> 5, cg = t & 31, rg4 = rg * 4;
    const int rowbase = blockIdx.x * 32;
    const int ny = blockIdx.y;
    const float* W = ((ny < 2) ? aW : bW) + (ny & 1) * 128 * D_;
    float* out = (ny < 2) ? g_a : g_bv;
    const int colbase = (ny & 1) * 128;

    for (int idx = t; idx < 32 * 128; idx += 256) {
        int row = idx >> 7, kk = idx & 127;
        As[row][kk] = g_h[(rowbase + row) * D_ + kk];
    }
    if (t < 32) scl[t] = g_scale[rowbase + t];

    ull acc[4][2];
#pragma unroll
    for (int i = 0; i < 4; i++) { acc[i][0] = 0ull; acc[i][1] = 0ull; }

    for (int kc = 0; kc < 4; kc++) {
        for (int idx = t; idx < 32 * 128; idx += 256) {
            int n = idx >> 5, kk = idx & 31;
            int gk = kc * 32 + kk;
            float v = W[n * D_ + gk] * nw[gk];
            int up = (n >> 2) ^ kk;
            Ws[kk][(up << 2) | (n & 3)] = v;
        }
        __syncthreads();
#pragma unroll
        for (int k4 = 0; k4 < 8; k4++) {
            float4 av4[4];
#pragma unroll
            for (int i = 0; i < 4; i++)
                av4[i] = *reinterpret_cast<const float4*>(&As[rg4 + i][kc * 32 + k4 * 4]);
#pragma unroll
            for (int q = 0; q < 4; q++) {
                int kk = k4 * 4 + q;
                ulonglong2 wv = *reinterpret_cast<const ulonglong2*>(&Ws[kk][(cg ^ kk) << 2]);
#pragma unroll
                for (int i = 0; i < 4; i++) {
                    float a = ((const float*)&av4[i])[q];
                    ull ap = pk2(a, a);
                    acc[i][0] = f2fma(ap, wv.x, acc[i][0]);
                    acc[i][1] = f2fma(ap, wv.y, acc[i][1]);
                }
            }
        }
        __syncthreads();
    }
#pragma unroll
    for (int i = 0; i < 4; i++) {
        int grow = rowbase + rg4 + i;
        float s = scl[rg4 + i];
        float2 v0 = upk2(acc[i][0]), v1 = upk2(acc[i][1]);
        float4 o4 = make_float4(v0.x * s, v0.y * s, v1.x * s, v1.y * s);
        *reinterpret_cast<float4*>(&out[grow * INNER_ + colbase + (cg << 2)]) = o4;
    }
}

// =====================================================================
// Kernel 3: conv + silu + CHUNKED PARALLEL selective scan + b-gate.
// Linear recurrence s_k = a*s_{k-1} + b*u_k split into 5 chunks of 25:
// each thread does a zero-init local scan; chunk-end states combined via
// smem; correction y_k += gamma * a^(q+1) * carry. 5x parallelism.
// Reads g_a/g_bv, writes g_u (no in-place race across chunks).
// Block: 160 threads = 32 channels x 5 chunks. Grid: 32 b x 8 groups.
// =====================================================================
__global__ __launch_bounds__(160) void k_convscan(const float* __restrict__ cw,
                                                  const float* __restrict__ cb,
                                                  const float* __restrict__ al,
                                                  const float* __restrict__ be,
                                                  const float* __restrict__ ga,
                                                  const float* __restrict__ de) {
    __shared__ float ends[5][32];
    const int t = threadIdx.x;
    const int ch = t & 31, ck = t >> 5;          // channel-in-group, chunk
    const int b = blockIdx.x >> 3;
    const int ig = blockIdx.x & 7;
    const int i = ig * 32 + ch;
    const int base = b * 125 * INNER_ + i;
    const int k0 = ck * 25;

    const float* w = cw + i * 5;
    const float w0 = w[0], w1 = w[1], w2 = w[2], w3 = w[3], w4 = w[4];
    const float bias = cb[i];
    const float siga = 1.f / (1.f + __expf(-al[i]));
    const float bb = be[i], gg = ga[i], dd = de[i];

    // load conv window k0-2 .. k0+26 (29 values), clipped to [0,124]
    float av[29];
#pragma unroll
    for (int q = 0; q < 29; q++) {
        int kk = k0 - 2 + q;
        av[q] = (kk >= 0 && kk <= 124) ? g_a[base + kk * INNER_] : 0.f;
    }

    // conv + silu + zero-init local scan; tv = gamma*s_local + delta*u
    float tv[25];
    float s = 0.f;
#pragma unroll
    for (int q = 0; q < 25; q++) {
        float acc = bias;
        acc = fmaf(w0, av[q], acc);
        acc = fmaf(w1, av[q + 1], acc);
        acc = fmaf(w2, av[q + 2], acc);
        acc = fmaf(w3, av[q + 3], acc);
        acc = fmaf(w4, av[q + 4], acc);
        float u = acc / (1.f + __expf(-acc));
        s = fmaf(siga, s, bb * u);
        tv[q] = fmaf(gg, s, dd * u);
    }
    ends[ck][ch] = s;
    __syncthreads();

    // carry into this chunk = true end-state of chunk ck-1
    float p2 = siga * siga, p4 = p2 * p2, p8 = p4 * p4, p16 = p8 * p8;
    float a25 = p16 * p8 * siga;
    float st = 0.f;
    for (int jj = 0; jj < ck; jj++)
        st = fmaf(a25, st, ends[jj][ch]);
    float gc = gg * st;

    // corrected output * b-gate -> g_u
    float pw = siga;
#pragma unroll
    for (int q = 0; q < 25; q++) {
        float bv = g_bv[base + (k0 + q) * INNER_];
        g_u[base + (k0 + q) * INNER_] = fmaf(gc, pw, tv[q]) * bv;
        pw *= siga;
    }
}

// =====================================================================
// Kernel 4: out-projection + DOUBLED residual (h <- 2h + y); epilogue
// computes next rmsnorm scale. Reads gated scan output from g_u.
// =====================================================================
__global__ __launch_bounds__(256) void k_outproj(const float* __restrict__ oW) {
    __shared__ __align__(16) float As[32][256];
    __shared__ __align__(16) float Ws[32][128];
    const int t = threadIdx.x, rg = t >> 5, cg = t & 31, rg4 = rg * 4;
    const int rowbase = blockIdx.x * 32;

    for (int idx = t; idx < 32 * 256; idx += 256) {
        int row = idx >> 8, kk = idx & 255;
        As[row][kk] = g_u[(rowbase + row) * INNER_ + kk];
    }

    ull acc[4][2];
#pragma unroll
    for (int i = 0; i < 4; i++) { acc[i][0] = 0ull; acc[i][1] = 0ull; }

    for (int kc = 0; kc < 8; kc++) {
        for (int idx = t; idx < 32 * 128; idx += 256) {
            int n = idx >> 5, kk = idx & 31;
            float v = oW[n * INNER_ + kc * 32 + kk];
            int up = (n >> 2) ^ kk;
            Ws[kk][(up << 2) | (n & 3)] = v;
        }
        __syncthreads();
#pragma unroll
        for (int k4 = 0; k4 < 8; k4++) {
            float4 av4[4];
#pragma unroll
            for (int i = 0; i < 4; i++)
                av4[i] = *reinterpret_cast<const float4*>(&As[rg4 + i][kc * 32 + k4 * 4]);
#pragma unroll
            for (int q = 0; q < 4; q++) {
                int kk = k4 * 4 + q;
                ulonglong2 wv = *reinterpret_cast<const ulonglong2*>(&Ws[kk][(cg ^ kk) << 2]);
#pragma unroll
                for (int i = 0; i < 4; i++) {
                    float a = ((const float*)&av4[i])[q];
                    ull ap = pk2(a, a);
                    acc[i][0] = f2fma(ap, wv.x, acc[i][0]);
                    acc[i][1] = f2fma(ap, wv.y, acc[i][1]);
                }
            }
        }
        __syncthreads();
    }
#pragma unroll
    for (int i = 0; i < 4; i++) {
        int grow = rowbase + rg4 + i;
        float4 hv = *reinterpret_cast<const float4*>(&g_h[grow * D_ + (cg << 2)]);
        float2 v0 = upk2(acc[i][0]), v1 = upk2(acc[i][1]);
        float4 nv = make_float4(2.f * hv.x + v0.x, 2.f * hv.y + v0.y,
                                2.f * hv.z + v1.x, 2.f * hv.w + v1.y);
        *reinterpret_cast<float4*>(&g_h[grow * D_ + (cg << 2)]) = nv;
        float ssq = nv.x * nv.x + nv.y * nv.y + nv.z * nv.z + nv.w * nv.w;
#pragma unroll
        for (int off = 16; off > 0; off >>= 1)
            ssq += __shfl_xor_sync(0xffffffffu, ssq, off);
        if (cg == 0) g_scale[grow] = rsqrtf(ssq * (1.0f / 128.0f) + EPS_);
    }
}

// =====================================================================
// Kernel 5a: materialize normalized flat activations once into g_u
// =====================================================================
__global__ __launch_bounds__(256) void k_normflat(const float* __restrict__ nfw) {
    int idx = blockIdx.x * 256 + threadIdx.x;   // 128000 float4 groups (grid 500)
    float sc = g_scale[idx >> 5];
    int j4 = idx << 2;
    float4 h = *reinterpret_cast<const float4*>(&g_h[j4]);
    float4 nv = *reinterpret_cast<const float4*>(&nfw[j4 & 127]);
    float4 r = make_float4(h.x * sc * nv.x, h.y * sc * nv.y,
                           h.z * sc * nv.z, h.w * sc * nv.w);
    *reinterpret_cast<float4*>(&g_u[j4]) = r;
}

// =====================================================================
// Kernel 5b: final GEMM  y[32,6144] = flat[32,16000] @ out_W^T
// Block: 128 outputs x 32 batches, split-K 640. The ENTIRE 640x32 flat
// slab is resident in smem (loaded once); weights double-buffered via
// cp.async in 32-k stages. Thread tile 4o x 4b; one sync per stage.
// =====================================================================
__global__ __launch_bounds__(256) void k_final(const float* __restrict__ outW) {
    __shared__ __align__(16) float fs[32][648];     // 640 + 8 pad (bank rotate)
    __shared__ __align__(16) float ws[2][128][36];  // 32 k + 4 pad per o row

    const int t = threadIdx.x;
    const int w = t >> 5, lane = t & 31;
    const int o_l = lane >> 2, b_l = lane & 3;
    const int o_t = (w >> 1) * 32 + o_l * 4;        // 4 consecutive o
    const int b_t = (w & 1) * 16 + b_l;             // batches b_t + 4j
    const int obase = blockIdx.x * 128;
    const int ks = blockIdx.y;
    const int jbase = ks * 640;

    const unsigned fs_base = (unsigned)__cvta_generic_to_shared(&fs[0][0]);
    const unsigned ws_base = (unsigned)__cvta_generic_to_shared(&ws[0][0][0]);

    // stage whole flat slab: 32 b x 640 k = 5120 16B-chunks
#pragma unroll
    for (int q = 0; q < 20; q++) {
        int c = t + 256 * q;
        int b = c / 160, kc = c - b * 160;
        cp16(fs_base + ((b * 648 + kc * 4) << 2), g_u + b * DNP_ + jbase + kc * 4);
    }
    // stage ws(0)
#pragma unroll
    for (int q = 0; q < 4; q++) {
        int c = t + 256 * q;
        int o = c >> 3, kc = c & 7;
        cp16(ws_base + ((o * 36 + kc * 4) << 2),
             outW + (size_t)(obase + o) * DNP_ + jbase + kc * 4);
    }
    cp_commit();

    ull acc[4][4];
#pragma unroll
    for (int i = 0; i < 4; i++)
#pragma unroll
        for (int j = 0; j < 4; j++) acc[i][j] = 0ull;

    cp_waitall();
    __syncthreads();

    for (int s = 0; s < 20; s++) {
        const int buf = s & 1;
        if (s + 1 < 20) {
#pragma unroll
            for (int q = 0; q < 4; q++) {
                int c = t + 256 * q;
                int o = c >> 3, kc = c & 7;
                cp16(ws_base + ((((buf ^ 1) * 128 + o) * 36 + kc * 4) << 2),
                     outW + (size_t)(obase + o) * DNP_ + jbase + (s + 1) * 32 + kc * 4);
            }
            cp_commit();
        }

        const int kb = s * 32;
#pragma unroll
        for (int kk = 0; kk < 8; kk++) {
            ulonglong2 wv[4];
#pragma unroll
            for (int i = 0; i < 4; i++)
                wv[i] = *reinterpret_cast<const ulonglong2*>(
                    &ws[buf][o_t + i][kk * 4]);
#pragma unroll
            for (int j = 0; j < 4; j++) {
                ulonglong2 fv = *reinterpret_cast<const ulonglong2*>(
                    &fs[b_t + 4 * j][kb + kk * 4]);
#pragma unroll
                for (int i = 0; i < 4; i++) {
                    acc[i][j] = f2fma(fv.x, wv[i].x, acc[i][j]);
                    acc[i][j] = f2fma(fv.y, wv[i].y, acc[i][j]);
                }
            }
        }
        cp_waitall();
        __syncthreads();
    }

#pragma unroll
    for (int j = 0; j < 4; j++) {
        int b = b_t + 4 * j;
        float4 v;
#pragma unroll
        for (int i = 0; i < 4; i++) {
            float2 p = upk2(acc[i][j]);
            ((float*)&v)[i] = p.x + p.y;
        }
        *reinterpret_cast<float4*>(&g_part[(ks * B_ + b) * CF_ + obase + o_t]) = v;
    }
}

// Kernel 6: reduce split-K partials + bias -> d_out (deterministic)
__global__ __launch_bounds__(256) void k_reduce(const float* __restrict__ outb,
                                                float* __restrict__ out) {
    int idx = blockIdx.x * 256 + threadIdx.x;   // 196608 = 768*256 exact
    int b = idx / CF_, o = idx - b * CF_;
    float v = outb[o];
#pragma unroll
    for (int s = 0; s < KS_; s++) v += g_part[(s * B_ + b) * CF_ + o];
    out[idx] = v;
}

// =====================================================================
extern "C" void kernel_launch(void* const* d_in, const int* in_sizes, int n_in,
                              void* d_out, int out_size) {
    const float* x     = (const float*)d_in[0];
    const float* peW   = (const float*)d_in[1];
    const float* peb   = (const float*)d_in[2];
    const float* normw = (const float*)d_in[3];
    const float* ipaW  = (const float*)d_in[4];
    const float* ipbW  = (const float*)d_in[5];
    const float* convW = (const float*)d_in[6];
    const float* convb = (const float*)d_in[7];
    const float* alp   = (const float*)d_in[8];
    const float* bet   = (const float*)d_in[9];
    const float* gam   = (const float*)d_in[10];
    const float* del   = (const float*)d_in[11];
    const float* opW   = (const float*)d_in[12];
    const float* normf = (const float*)d_in[13];
    const float* outW  = (const float*)d_in[14];
    const float* outb  = (const float*)d_in[15];
    float* out = (float*)d_out;

    k_pe<<<NP_, 128>>>();
    k_embed<<<M_ / 32, 256>>>(x, peW, peb);
    for (int l = 0; l < 4; l++) {
        k_inproj<<<dim3(M_ / 32, 4), 256>>>(ipaW + l * INNER_ * D_,
                                            ipbW + l * INNER_ * D_,
                                            normw + l * D_);
        k_convscan<<<B_ * 8, 160>>>(convW + l * INNER_ * 5, convb + l * INNER_,
                                    alp + l * INNER_, bet + l * INNER_,
                                    gam + l * INNER_, del + l * INNER_);
        k_outproj<<<M_ / 32, 256>>>(opW + l * D_ * INNER_);
    }
    k_normflat<<<500, 256>>>(normf);
    k_final<<<dim3(CF_ / 128, KS_), 256>>>(outW);
    k_reduce<<<(B_ * CF_) / 256, 256>>>(outb, out);
}

// round 7
// speedup vs baseline: 2.1175x; 1.2698x over previous
#include <cuda_runtime.h>
#include <cuda_bf16.h>
#include <math.h>

using ull = unsigned long long;

constexpr int B_   = 32;
constexpr int C_   = 64;
constexpr int L_   = 512;
constexpr int S_   = 4;
constexpr int NP_  = 125;
constexpr int D_   = 128;
constexpr int INNER_ = 256;
constexpr int CP_  = 1024;        // C*P
constexpr int M_   = B_ * NP_;    // 4000
constexpr int CF_  = 6144;        // C*F
constexpr int DNP_ = 16000;       // D*NP
constexpr int KS_  = 50;          // split-K for final GEMM (320 k each)
constexpr float EPS_ = 1e-5f;

// -------- device scratch (no allocation allowed) --------
__device__ float g_h[M_ * D_];          // hidden (B,NP,D) contiguous == flat layout
__device__ float g_scale[M_];           // rmsnorm scale per row (for NEXT consumer)
__device__ float g_a[M_ * INNER_];      // in-proj a
__device__ float g_bv[M_ * INNER_];     // in-proj b
__device__ float g_u[M_ * INNER_];      // gated scan out
__device__ float g_part[KS_ * B_ * CF_];// split-K partials (39MB)
__device__ float g_pe[NP_ * D_];        // accurate sincos PE table
__device__ __nv_bfloat16 g_fhi[B_ * DNP_];  // normalized flat, bf16 hi
__device__ __nv_bfloat16 g_flo[B_ * DNP_];  // normalized flat, bf16 lo

// -------- f32x2 helpers (Blackwell packed fp32) --------
__device__ __forceinline__ ull pk2(float lo, float hi) {
    ull r; asm("mov.b64 %0,{%1,%2};" : "=l"(r) : "f"(lo), "f"(hi)); return r;
}
__device__ __forceinline__ ull f2fma(ull a, ull b, ull c) {
    ull d; asm("fma.rn.f32x2 %0,%1,%2,%3;" : "=l"(d) : "l"(a), "l"(b), "l"(c)); return d;
}
__device__ __forceinline__ float2 upk2(ull v) {
    float2 r; asm("mov.b64 {%0,%1},%2;" : "=f"(r.x), "=f"(r.y) : "l"(v)); return r;
}
__device__ __forceinline__ void cp16(unsigned s, const float* g) {
    asm volatile("cp.async.cg.shared.global [%0],[%1],16;" :: "r"(s), "l"(g));
}
__device__ __forceinline__ void cp_commit() { asm volatile("cp.async.commit_group;"); }
__device__ __forceinline__ void cp_waitall() { asm volatile("cp.async.wait_group 0;" ::: "memory"); }

// bf16 mma m16n8k16 row.col f32 accumulate
__device__ __forceinline__ void mma_bf16(float* c, unsigned a0, unsigned a1,
                                         unsigned a2, unsigned a3,
                                         unsigned b0, unsigned b1) {
    asm volatile(
        "mma.sync.aligned.m16n8k16.row.col.f32.bf16.bf16.f32 "
        "{%0,%1,%2,%3}, {%4,%5,%6,%7}, {%8,%9}, {%0,%1,%2,%3};"
        : "+f"(c[0]), "+f"(c[1]), "+f"(c[2]), "+f"(c[3])
        : "r"(a0), "r"(a1), "r"(a2), "r"(a3), "r"(b0), "r"(b1));
}

// =====================================================================
// Kernel 0: accurate sincos PE table
// =====================================================================
__global__ __launch_bounds__(128) void k_pe() {
    int idx = blockIdx.x * 128 + threadIdx.x;   // 125*128 = 16000 exact
    int kq = idx >> 7, col = idx & 127;
    int ii = col >> 1;
    float targ = (-9.210340371976184f) * (float)ii * (1.0f / 64.0f);
    float divf = (float)exp((double)targ);
    float ang = (float)kq * divf;               // fp32 rounding like reference
    double a = (double)ang;
    g_pe[idx] = (float)((col & 1) ? cos(a) : sin(a));
}

// =====================================================================
// Kernel 1: patch embed GEMM + bias + sincos PE; epilogue -> rmsnorm scale
// =====================================================================
__global__ __launch_bounds__(256) void k_embed(const float* __restrict__ x,
                                               const float* __restrict__ peW,
                                               const float* __restrict__ peb) {
    __shared__ __align__(16) float As[32][64];
    __shared__ __align__(16) float Ws[64][128];  // XOR-swizzled, k-major
    const int t = threadIdx.x, rg = t >> 5, cg = t & 31, rg4 = rg * 4;
    const int rowbase = blockIdx.x * 32;

    ull acc[4][2];
#pragma unroll
    for (int i = 0; i < 4; i++) { acc[i][0] = 0ull; acc[i][1] = 0ull; }

    for (int kc = 0; kc < 16; kc++) {
        for (int idx = t; idx < 32 * 64; idx += 256) {
            int row = idx >> 6, kk = idx & 63;
            int gk = kc * 64 + kk, c = gk >> 4, p = gk & 15;
            int grow = rowbase + row;
            int bb = grow / 125, kq = grow - bb * 125;
            As[row][kk] = x[(bb * C_ + c) * L_ + kq * S_ + p];
        }
        for (int idx = t; idx < 64 * 128; idx += 256) {
            int d = idx >> 6, kk = idx & 63;
            float v = peW[d * CP_ + kc * 64 + kk];
            int up = (d >> 2) ^ (kk & 31);
            Ws[kk][(up << 2) | (d & 3)] = v;
        }
        __syncthreads();
#pragma unroll
        for (int k4 = 0; k4 < 16; k4++) {
            float4 av4[4];
#pragma unroll
            for (int i = 0; i < 4; i++)
                av4[i] = *reinterpret_cast<const float4*>(&As[rg4 + i][k4 * 4]);
#pragma unroll
            for (int q = 0; q < 4; q++) {
                int kk = k4 * 4 + q;
                ulonglong2 wv = *reinterpret_cast<const ulonglong2*>(
                    &Ws[kk][(cg ^ (kk & 31)) << 2]);
#pragma unroll
                for (int i = 0; i < 4; i++) {
                    float a = ((const float*)&av4[i])[q];
                    ull ap = pk2(a, a);
                    acc[i][0] = f2fma(ap, wv.x, acc[i][0]);
                    acc[i][1] = f2fma(ap, wv.y, acc[i][1]);
                }
            }
        }
        __syncthreads();
    }

#pragma unroll
    for (int i = 0; i < 4; i++) {
        int grow = rowbase + rg4 + i;
        int bb = grow / 125, kq = grow - bb * 125;
        float2 v0 = upk2(acc[i][0]), v1 = upk2(acc[i][1]);
        float vals[4] = {v0.x, v0.y, v1.x, v1.y};
        float4 pe4 = *reinterpret_cast<const float4*>(&g_pe[kq * D_ + (cg << 2)]);
        float4 pb4 = *reinterpret_cast<const float4*>(&peb[cg << 2]);
        float4 outv;
        float ssq = 0.f;
#pragma unroll
        for (int j = 0; j < 4; j++) {
            float v = vals[j] + ((const float*)&pb4)[j] + ((const float*)&pe4)[j];
            ((float*)&outv)[j] = v;
            ssq += v * v;
        }
        *reinterpret_cast<float4*>(&g_h[grow * D_ + (cg << 2)]) = outv;
#pragma unroll
        for (int off = 16; off > 0; off >>= 1)
            ssq += __shfl_xor_sync(0xffffffffu, ssq, off);
        if (cg == 0) g_scale[grow] = rsqrtf(ssq * (1.0f / 128.0f) + EPS_);
    }
}

// =====================================================================
// Kernel 2: fused rmsnorm + in-projections a,b  (M=4000, K=128, N=2x256)
// =====================================================================
__global__ __launch_bounds__(256) void k_inproj(const float* __restrict__ aW,
                                                const float* __restrict__ bW,
                                                const float* __restrict__ nw) {
    __shared__ __align__(16) float As[32][128];
    __shared__ __align__(16) float Ws[32][128];
    __shared__ float scl[32];
    const int t = threadIdx.x, rg = t >> 5, cg = t & 31, rg4 = rg * 4;
    const int rowbase = blockIdx.x * 32;
    const int ny = blockIdx.y;
    const float* W = ((ny < 2) ? aW : bW) + (ny & 1) * 128 * D_;
    float* out = (ny < 2) ? g_a : g_bv;
    const int colbase = (ny & 1) * 128;

    for (int idx = t; idx < 32 * 128; idx += 256) {
        int row = idx >> 7, kk = idx & 127;
        As[row][kk] = g_h[(rowbase + row) * D_ + kk];
    }
    if (t < 32) scl[t] = g_scale[rowbase + t];

    ull acc[4][2];
#pragma unroll
    for (int i = 0; i < 4; i++) { acc[i][0] = 0ull; acc[i][1] = 0ull; }

    for (int kc = 0; kc < 4; kc++) {
        for (int idx = t; idx < 32 * 128; idx += 256) {
            int n = idx >> 5, kk = idx & 31;
            int gk = kc * 32 + kk;
            float v = W[n * D_ + gk] * nw[gk];
            int up = (n >> 2) ^ kk;
            Ws[kk][(up << 2) | (n & 3)] = v;
        }
        __syncthreads();
#pragma unroll
        for (int k4 = 0; k4 < 8; k4++) {
            float4 av4[4];
#pragma unroll
            for (int i = 0; i < 4; i++)
                av4[i] = *reinterpret_cast<const float4*>(&As[rg4 + i][kc * 32 + k4 * 4]);
#pragma unroll
            for (int q = 0; q < 4; q++) {
                int kk = k4 * 4 + q;
                ulonglong2 wv = *reinterpret_cast<const ulonglong2*>(&Ws[kk][(cg ^ kk) << 2]);
#pragma unroll
                for (int i = 0; i < 4; i++) {
                    float a = ((const float*)&av4[i])[q];
                    ull ap = pk2(a, a);
                    acc[i][0] = f2fma(ap, wv.x, acc[i][0]);
                    acc[i][1] = f2fma(ap, wv.y, acc[i][1]);
                }
            }
        }
        __syncthreads();
    }
#pragma unroll
    for (int i = 0; i < 4; i++) {
        int grow = rowbase + rg4 + i;
        float s = scl[rg4 + i];
        float2 v0 = upk2(acc[i][0]), v1 = upk2(acc[i][1]);
        float4 o4 = make_float4(v0.x * s, v0.y * s, v1.x * s, v1.y * s);
        *reinterpret_cast<float4*>(&out[grow * INNER_ + colbase + (cg << 2)]) = o4;
    }
}

// =====================================================================
// Kernel 3: conv + silu + chunked parallel scan + b-gate.
// 25 chunks of 5 positions; block = 32 channels x 25 chunks = 800 thr.
// Grid: 32 b x 8 channel-groups = 256 blocks (204K threads).
// =====================================================================
__global__ __launch_bounds__(800) void k_convscan(const float* __restrict__ cw,
                                                  const float* __restrict__ cb,
                                                  const float* __restrict__ al,
                                                  const float* __restrict__ be,
                                                  const float* __restrict__ ga,
                                                  const float* __restrict__ de) {
    __shared__ float ends[25][32];
    const int t = threadIdx.x;
    const int ch = t & 31, ck = t >> 5;          // channel-in-group, chunk 0..24
    const int b = blockIdx.x >> 3;
    const int ig = blockIdx.x & 7;
    const int i = ig * 32 + ch;
    const int base = b * 125 * INNER_ + i;
    const int k0 = ck * 5;

    const float* w = cw + i * 5;
    const float w0 = w[0], w1 = w[1], w2 = w[2], w3 = w[3], w4 = w[4];
    const float bias = cb[i];
    const float siga = 1.f / (1.f + __expf(-al[i]));
    const float bb = be[i], gg = ga[i], dd = de[i];

    // conv window k0-2 .. k0+6 (9 values), clipped to [0,124]
    float av[9];
#pragma unroll
    for (int q = 0; q < 9; q++) {
        int kk = k0 - 2 + q;
        av[q] = (kk >= 0 && kk <= 124) ? g_a[base + kk * INNER_] : 0.f;
    }

    float tv[5];
    float s = 0.f;
#pragma unroll
    for (int q = 0; q < 5; q++) {
        float acc = bias;
        acc = fmaf(w0, av[q], acc);
        acc = fmaf(w1, av[q + 1], acc);
        acc = fmaf(w2, av[q + 2], acc);
        acc = fmaf(w3, av[q + 3], acc);
        acc = fmaf(w4, av[q + 4], acc);
        float u = acc / (1.f + __expf(-acc));
        s = fmaf(siga, s, bb * u);
        tv[q] = fmaf(gg, s, dd * u);
    }
    ends[ck][ch] = s;
    __syncthreads();

    // carry into this chunk (fold of prior chunk ends with a^5 weighting)
    float p2 = siga * siga, p4 = p2 * p2;
    float a5 = p4 * siga;
    float st = 0.f;
    for (int jj = 0; jj < ck; jj++)
        st = fmaf(a5, st, ends[jj][ch]);
    float gc = gg * st;

    float pw = siga;
#pragma unroll
    for (int q = 0; q < 5; q++) {
        float bv = g_bv[base + (k0 + q) * INNER_];
        g_u[base + (k0 + q) * INNER_] = fmaf(gc, pw, tv[q]) * bv;
        pw *= siga;
    }
}

// =====================================================================
// Kernel 4: out-projection + DOUBLED residual (h <- 2h + y); epilogue
// computes next rmsnorm scale. Reads gated scan output from g_u.
// =====================================================================
__global__ __launch_bounds__(256) void k_outproj(const float* __restrict__ oW) {
    __shared__ __align__(16) float As[32][256];
    __shared__ __align__(16) float Ws[32][128];
    const int t = threadIdx.x, rg = t >> 5, cg = t & 31, rg4 = rg * 4;
    const int rowbase = blockIdx.x * 32;

    for (int idx = t; idx < 32 * 256; idx += 256) {
        int row = idx >> 8, kk = idx & 255;
        As[row][kk] = g_u[(rowbase + row) * INNER_ + kk];
    }

    ull acc[4][2];
#pragma unroll
    for (int i = 0; i < 4; i++) { acc[i][0] = 0ull; acc[i][1] = 0ull; }

    for (int kc = 0; kc < 8; kc++) {
        for (int idx = t; idx < 32 * 128; idx += 256) {
            int n = idx >> 5, kk = idx & 31;
            float v = oW[n * INNER_ + kc * 32 + kk];
            int up = (n >> 2) ^ kk;
            Ws[kk][(up << 2) | (n & 3)] = v;
        }
        __syncthreads();
#pragma unroll
        for (int k4 = 0; k4 < 8; k4++) {
            float4 av4[4];
#pragma unroll
            for (int i = 0; i < 4; i++)
                av4[i] = *reinterpret_cast<const float4*>(&As[rg4 + i][kc * 32 + k4 * 4]);
#pragma unroll
            for (int q = 0; q < 4; q++) {
                int kk = k4 * 4 + q;
                ulonglong2 wv = *reinterpret_cast<const ulonglong2*>(&Ws[kk][(cg ^ kk) << 2]);
#pragma unroll
                for (int i = 0; i < 4; i++) {
                    float a = ((const float*)&av4[i])[q];
                    ull ap = pk2(a, a);
                    acc[i][0] = f2fma(ap, wv.x, acc[i][0]);
                    acc[i][1] = f2fma(ap, wv.y, acc[i][1]);
                }
            }
        }
        __syncthreads();
    }
#pragma unroll
    for (int i = 0; i < 4; i++) {
        int grow = rowbase + rg4 + i;
        float4 hv = *reinterpret_cast<const float4*>(&g_h[grow * D_ + (cg << 2)]);
        float2 v0 = upk2(acc[i][0]), v1 = upk2(acc[i][1]);
        float4 nv = make_float4(2.f * hv.x + v0.x, 2.f * hv.y + v0.y,
                                2.f * hv.z + v1.x, 2.f * hv.w + v1.y);
        *reinterpret_cast<float4*>(&g_h[grow * D_ + (cg << 2)]) = nv;
        float ssq = nv.x * nv.x + nv.y * nv.y + nv.z * nv.z + nv.w * nv.w;
#pragma unroll
        for (int off = 16; off > 0; off >>= 1)
            ssq += __shfl_xor_sync(0xffffffffu, ssq, off);
        if (cg == 0) g_scale[grow] = rsqrtf(ssq * (1.0f / 128.0f) + EPS_);
    }
}

// =====================================================================
// Kernel 5a: normalized flat activations -> bf16 hi/lo split slabs
// =====================================================================
__global__ __launch_bounds__(256) void k_flatcvt(const float* __restrict__ nfw) {
    int idx = blockIdx.x * 256 + threadIdx.x;   // 128000 groups of 4 (grid 500)
    float sc = g_scale[idx >> 5];
    int j4 = idx << 2;
    float4 h = *reinterpret_cast<const float4*>(&g_h[j4]);
    float4 nv = *reinterpret_cast<const float4*>(&nfw[j4 & 127]);
    float vv[4] = {h.x * sc * nv.x, h.y * sc * nv.y, h.z * sc * nv.z, h.w * sc * nv.w};
    __nv_bfloat16 hv[4], lv[4];
#pragma unroll
    for (int j = 0; j < 4; j++) {
        hv[j] = __float2bfloat16(vv[j]);
        lv[j] = __float2bfloat16(vv[j] - __bfloat162float(hv[j]));
    }
    *reinterpret_cast<ull*>(&g_fhi[j4]) = *reinterpret_cast<ull*>(hv);
    *reinterpret_cast<ull*>(&g_flo[j4]) = *reinterpret_cast<ull*>(lv);
}

// =====================================================================
// Kernel 5b: final GEMM via bf16 hi/lo split tensor MMA.
// y[32,6144] = flat[32,16000] @ out_W^T ; split-K 50 (320 k per block).
// Block: 128 outputs (8 warps x 16) x 32 batches. Activation slab (bf16
// hi+lo, 42KB) staged once via cp.async; weights stream fp32 straight
// from DRAM via per-fragment LDG.64 + in-register bf16 hi/lo conversion.
// 3 mma terms: Ahi*Whi + Ahi*Wlo + Alo*Whi (err ~2^-16).
// =====================================================================
__global__ __launch_bounds__(256) void k_final(const float* __restrict__ outW) {
    __shared__ __align__(16) __nv_bfloat16 fh[32][328];  // 320 + 8 pad
    __shared__ __align__(16) __nv_bfloat16 fl[32][328];

    const int t = threadIdx.x;
    const int w = t >> 5, l = t & 31;
    const int g = l >> 2, tig = l & 3;
    const int obase = blockIdx.x * 128;
    const int ks = blockIdx.y;
    const int jbase = ks * 320;

    // stage activation slabs (32 rows x 320 bf16 each): 1280 16B chunks each
    {
        unsigned fhb = (unsigned)__cvta_generic_to_shared(&fh[0][0]);
        unsigned flb = (unsigned)__cvta_generic_to_shared(&fl[0][0]);
#pragma unroll
        for (int q = 0; q < 5; q++) {
            int c = t + 256 * q;           // 0..1279
            int b = c / 40, kc = c - b * 40;
            cp16(fhb + b * 656 + kc * 16,
                 (const float*)(g_fhi + b * DNP_ + jbase + kc * 8));
            cp16(flb + b * 656 + kc * 16,
                 (const float*)(g_flo + b * DNP_ + jbase + kc * 8));
        }
    }
    cp_commit();

    // weight row pointers for this thread's two n-tiles
    const int n0 = obase + w * 16 + g;
    const float* w0p = outW + (size_t)n0 * DNP_ + jbase + 2 * tig;
    const float* w1p = w0p + (size_t)8 * DNP_;   // n0 + 8

    float c[2][2][4];
#pragma unroll
    for (int mt = 0; mt < 2; mt++)
#pragma unroll
        for (int nt = 0; nt < 2; nt++)
#pragma unroll
            for (int q = 0; q < 4; q++) c[mt][nt][q] = 0.f;

    // prefetch chunk 0 weights
    float2 cur[4] = { *reinterpret_cast<const float2*>(w0p),
                      *reinterpret_cast<const float2*>(w0p + 8),
                      *reinterpret_cast<const float2*>(w1p),
                      *reinterpret_cast<const float2*>(w1p + 8) };

    cp_waitall();
    __syncthreads();

    for (int ch = 0; ch < 20; ch++) {
        // prefetch next chunk (clamped; last-iter loads are discarded)
        int chn = (ch + 1 < 20) ? (ch + 1) : 19;
        float2 nxt[4] = { *reinterpret_cast<const float2*>(w0p + chn * 16),
                          *reinterpret_cast<const float2*>(w0p + chn * 16 + 8),
                          *reinterpret_cast<const float2*>(w1p + chn * 16),
                          *reinterpret_cast<const float2*>(w1p + chn * 16 + 8) };

        // A fragments (hi and lo) for both m-tiles
        const int off = ch * 16 + 2 * tig;
        unsigned ahi[2][4], alo[2][4];
#pragma unroll
        for (int mt = 0; mt < 2; mt++) {
            int r = g + mt * 16;
            ahi[mt][0] = *reinterpret_cast<const unsigned*>(&fh[r][off]);
            ahi[mt][1] = *reinterpret_cast<const unsigned*>(&fh[r + 8][off]);
            ahi[mt][2] = *reinterpret_cast<const unsigned*>(&fh[r][off + 8]);
            ahi[mt][3] = *reinterpret_cast<const unsigned*>(&fh[r + 8][off + 8]);
            alo[mt][0] = *reinterpret_cast<const unsigned*>(&fl[r][off]);
            alo[mt][1] = *reinterpret_cast<const unsigned*>(&fl[r + 8][off]);
            alo[mt][2] = *reinterpret_cast<const unsigned*>(&fl[r][off + 8]);
            alo[mt][3] = *reinterpret_cast<const unsigned*>(&fl[r + 8][off + 8]);
        }

        // convert W fp32 -> bf16 hi/lo fragments  (b0: k pair, b1: k+8 pair)
        unsigned bhi[2][2], blo[2][2];
#pragma unroll
        for (int nt = 0; nt < 2; nt++) {
#pragma unroll
            for (int hb = 0; hb < 2; hb++) {
                float2 wv = cur[nt * 2 + hb];
                __nv_bfloat162 h2 = __floats2bfloat162_rn(wv.x, wv.y);
                float2 lo2 = make_float2(wv.x - __bfloat162float(__low2bfloat16(h2)),
                                         wv.y - __bfloat162float(__high2bfloat16(h2)));
                __nv_bfloat162 l2 = __floats2bfloat162_rn(lo2.x, lo2.y);
                bhi[nt][hb] = *reinterpret_cast<unsigned*>(&h2);
                blo[nt][hb] = *reinterpret_cast<unsigned*>(&l2);
            }
        }

#pragma unroll
        for (int mt = 0; mt < 2; mt++)
#pragma unroll
            for (int nt = 0; nt < 2; nt++) {
                mma_bf16(c[mt][nt], ahi[mt][0], ahi[mt][1], ahi[mt][2], ahi[mt][3],
                         bhi[nt][0], bhi[nt][1]);
                mma_bf16(c[mt][nt], ahi[mt][0], ahi[mt][1], ahi[mt][2], ahi[mt][3],
                         blo[nt][0], blo[nt][1]);
                mma_bf16(c[mt][nt], alo[mt][0], alo[mt][1], alo[mt][2], alo[mt][3],
                         bhi[nt][0], bhi[nt][1]);
            }

#pragma unroll
        for (int q = 0; q < 4; q++) cur[q] = nxt[q];
    }

    // epilogue: C[row g / g+8][2tig, 2tig+1] per tile
#pragma unroll
    for (int mt = 0; mt < 2; mt++)
#pragma unroll
        for (int nt = 0; nt < 2; nt++) {
            int o = obase + w * 16 + nt * 8 + 2 * tig;
            int b0 = g + mt * 16;
            float* p0 = &g_part[(ks * B_ + b0) * CF_ + o];
            float* p1 = &g_part[(ks * B_ + b0 + 8) * CF_ + o];
            *reinterpret_cast<float2*>(p0) = make_float2(c[mt][nt][0], c[mt][nt][1]);
            *reinterpret_cast<float2*>(p1) = make_float2(c[mt][nt][2], c[mt][nt][3]);
        }
}

// Kernel 6: reduce split-K partials + bias -> d_out (deterministic)
__global__ __launch_bounds__(256) void k_reduce(const float* __restrict__ outb,
                                                float* __restrict__ out) {
    int idx = blockIdx.x * 256 + threadIdx.x;   // 196608 = 768*256 exact
    int b = idx / CF_, o = idx - b * CF_;
    float v = outb[o];
#pragma unroll
    for (int s = 0; s < KS_; s++) v += g_part[(s * B_ + b) * CF_ + o];
    out[idx] = v;
}

// =====================================================================
extern "C" void kernel_launch(void* const* d_in, const int* in_sizes, int n_in,
                              void* d_out, int out_size) {
    const float* x     = (const float*)d_in[0];
    const float* peW   = (const float*)d_in[1];
    const float* peb   = (const float*)d_in[2];
    const float* normw = (const float*)d_in[3];
    const float* ipaW  = (const float*)d_in[4];
    const float* ipbW  = (const float*)d_in[5];
    const float* convW = (const float*)d_in[6];
    const float* convb = (const float*)d_in[7];
    const float* alp   = (const float*)d_in[8];
    const float* bet   = (const float*)d_in[9];
    const float* gam   = (const float*)d_in[10];
    const float* del   = (const float*)d_in[11];
    const float* opW   = (const float*)d_in[12];
    const float* normf = (const float*)d_in[13];
    const float* outW  = (const float*)d_in[14];
    const float* outb  = (const float*)d_in[15];
    float* out = (float*)d_out;

    k_pe<<<NP_, 128>>>();
    k_embed<<<M_ / 32, 256>>>(x, peW, peb);
    for (int l = 0; l < 4; l++) {
        k_inproj<<<dim3(M_ / 32, 4), 256>>>(ipaW + l * INNER_ * D_,
                                            ipbW + l * INNER_ * D_,
                                            normw + l * D_);
        k_convscan<<<B_ * 8, 800>>>(convW + l * INNER_ * 5, convb + l * INNER_,
                                    alp + l * INNER_, bet + l * INNER_,
                                    gam + l * INNER_, del + l * INNER_);
        k_outproj<<<M_ / 32, 256>>>(opW + l * D_ * INNER_);
    }
    k_flatcvt<<<500, 256>>>(normf);
    k_final<<<dim3(CF_ / 128, KS_), 256>>>(outW);
    k_reduce<<<(B_ * CF_) / 256, 256>>>(outb, out);
}

// round 8
// speedup vs baseline: 3.0681x; 1.4489x over previous
#include <cuda_runtime.h>
#include <cuda_bf16.h>
#include <math.h>

using ull = unsigned long long;
using bf = __nv_bfloat16;

constexpr int B_   = 32;
constexpr int C_   = 64;
constexpr int L_   = 512;
constexpr int NP_  = 125;
constexpr int D_   = 128;
constexpr int INNER_ = 256;
constexpr int M_   = B_ * NP_;    // 4000
constexpr int CF_  = 6144;        // C*F
constexpr int DNP_ = 16000;       // D*NP
constexpr int KS_  = 50;          // split-K for final GEMM (320 k each)
constexpr float EPS_ = 1e-5f;

// weight slab offsets (bf16 hi/lo converted once per launch)
constexpr int WOFF_EMB = 0;                 // 128 x 1024
constexpr int WSZ_EMB  = 128 * 1024;
constexpr int WSZ_LAYER = 2 * 256 * 128 + 128 * 256;  // ipa+ipb + op = 98304
constexpr int WTOT = WSZ_EMB + 4 * WSZ_LAYER;         // 524288

// -------- device scratch (no allocation allowed) --------
__device__ float g_h[M_ * D_];          // hidden (fp32, residual base)
__device__ float g_scale[M_];           // rmsnorm scale per row (final norm)
__device__ float g_a[M_ * INNER_];      // in-proj a
__device__ float g_bv[M_ * INNER_];     // in-proj b
__device__ float g_u[M_ * INNER_];      // gated scan out
__device__ float g_part[KS_ * B_ * CF_];// split-K partials
__device__ float g_pe[NP_ * D_];        // accurate sincos PE table
__device__ bf g_fhi[B_ * DNP_];         // normalized flat, bf16 hi
__device__ bf g_flo[B_ * DNP_];         // normalized flat, bf16 lo
__device__ bf g_nhh[M_ * D_];           // normalized hidden, bf16 hi
__device__ bf g_nhl[M_ * D_];           // normalized hidden, bf16 lo
__device__ bf g_wbh[WTOT];              // weights bf16 hi
__device__ bf g_wbl[WTOT];              // weights bf16 lo

__device__ __forceinline__ void cp16(unsigned s, const void* g) {
    asm volatile("cp.async.cg.shared.global [%0],[%1],16;" :: "r"(s), "l"(g));
}
__device__ __forceinline__ void cp_commit() { asm volatile("cp.async.commit_group;"); }
__device__ __forceinline__ void cp_waitall() { asm volatile("cp.async.wait_group 0;" ::: "memory"); }

// bf16 mma m16n8k16 row.col f32 accumulate (validated in round 7)
__device__ __forceinline__ void mma_bf16(float* c, const unsigned* a,
                                         unsigned b0, unsigned b1) {
    asm volatile(
        "mma.sync.aligned.m16n8k16.row.col.f32.bf16.bf16.f32 "
        "{%0,%1,%2,%3}, {%4,%5,%6,%7}, {%8,%9}, {%0,%1,%2,%3};"
        : "+f"(c[0]), "+f"(c[1]), "+f"(c[2]), "+f"(c[3])
        : "r"(a[0]), "r"(a[1]), "r"(a[2]), "r"(a[3]), "r"(b0), "r"(b1));
}
__device__ __forceinline__ unsigned ldu32(const bf* p) {
    return *reinterpret_cast<const unsigned*>(p);
}
__device__ __forceinline__ void split_bf(float v, bf& h, bf& l) {
    h = __float2bfloat16(v);
    l = __float2bfloat16(v - __bfloat162float(h));
}

// =====================================================================
// Kernel 0a: accurate sincos PE table
// =====================================================================
__global__ __launch_bounds__(128) void k_pe() {
    int idx = blockIdx.x * 128 + threadIdx.x;   // 16000 exact
    int kq = idx >> 7, col = idx & 127;
    int ii = col >> 1;
    float targ = (-9.210340371976184f) * (float)ii * (1.0f / 64.0f);
    float divf = (float)exp((double)targ);
    float ang = (float)kq * divf;
    double a = (double)ang;
    g_pe[idx] = (float)((col & 1) ? cos(a) : sin(a));
}

// =====================================================================
// Kernel 0b: weight prep — fp32 (optionally * nw[k]) -> bf16 hi/lo slabs
// =====================================================================
__global__ __launch_bounds__(256) void k_prepw(const float* __restrict__ src,
                                               const float* __restrict__ nw,
                                               int dstoff, int kmask) {
    int idx = blockIdx.x * 256 + threadIdx.x;
    float v = src[idx];
    if (nw) v *= nw[idx & kmask];
    bf h, l; split_bf(v, h, l);
    g_wbh[dstoff + idx] = h;
    g_wbl[dstoff + idx] = l;
}

// =====================================================================
// Kernel 1: patch-embed GEMM (bf16-split MMA) + bias + PE; epilogue
// writes g_h (pre-norm, residual base), g_scale, g_nhh/g_nhl.
// Block: 32 m-rows x 128 n, K=1024 in 32 chunks. 256 thr = 8 warps
// (2 m-groups x 4 n-quarters).
// =====================================================================
__global__ __launch_bounds__(256) void k_embed(const float* __restrict__ x,
                                               const float* __restrict__ peb) {
    __shared__ __align__(16) union {
        struct { bf ah[32][40], al[32][40], wh[128][40], wl[128][40]; } m;
        float hbuf[32][132];
    } s;
    const int t = threadIdx.x, lane = t & 31, w = t >> 5;
    const int mg = w >> 2, nq = w & 3;
    const int growb = blockIdx.x * 32;

    float acc[4][4] = {};

    for (int kch = 0; kch < 32; kch++) {
        // stage A: gather x + split
#pragma unroll
        for (int q = 0; q < 4; q++) {
            int idx = t + 256 * q;
            int row = idx >> 5, kk = idx & 31;
            int gk = kch * 32 + kk, c = gk >> 4, p = gk & 15;
            int grow = growb + row, bb = grow / 125, kq = grow - bb * 125;
            float v = x[(bb * C_ + c) * L_ + kq * 4 + p];
            split_bf(v, s.m.ah[row][kk], s.m.al[row][kk]);
        }
        // stage W via cp.async (bf16 slabs)
#pragma unroll
        for (int q = 0; q < 2; q++) {
            int idx = t + 256 * q;
            int row = idx >> 2, k4 = idx & 3;
            const bf* sh = g_wbh + WOFF_EMB + row * 1024 + kch * 32 + k4 * 8;
            const bf* sl = g_wbl + WOFF_EMB + row * 1024 + kch * 32 + k4 * 8;
            cp16((unsigned)__cvta_generic_to_shared(&s.m.wh[row][k4 * 8]), sh);
            cp16((unsigned)__cvta_generic_to_shared(&s.m.wl[row][k4 * 8]), sl);
        }
        cp_commit(); cp_waitall();
        __syncthreads();

#pragma unroll
        for (int kst = 0; kst < 2; kst++) {
            const int ko = kst * 16 + 2 * (lane & 3);
            const int r0 = mg * 16 + (lane >> 2);
            unsigned ah[4], al_[4];
            ah[0] = ldu32(&s.m.ah[r0][ko]);     ah[1] = ldu32(&s.m.ah[r0 + 8][ko]);
            ah[2] = ldu32(&s.m.ah[r0][ko + 8]); ah[3] = ldu32(&s.m.ah[r0 + 8][ko + 8]);
            al_[0] = ldu32(&s.m.al[r0][ko]);     al_[1] = ldu32(&s.m.al[r0 + 8][ko]);
            al_[2] = ldu32(&s.m.al[r0][ko + 8]); al_[3] = ldu32(&s.m.al[r0 + 8][ko + 8]);
#pragma unroll
            for (int nt = 0; nt < 4; nt++) {
                int n = nq * 32 + nt * 8 + (lane >> 2);
                unsigned bh0 = ldu32(&s.m.wh[n][ko]), bh1 = ldu32(&s.m.wh[n][ko + 8]);
                unsigned bl0 = ldu32(&s.m.wl[n][ko]), bl1 = ldu32(&s.m.wl[n][ko + 8]);
                mma_bf16(acc[nt], ah, bh0, bh1);
                mma_bf16(acc[nt], ah, bl0, bl1);
                mma_bf16(acc[nt], al_, bh0, bh1);
            }
        }
        __syncthreads();
    }

    // frags -> hbuf
#pragma unroll
    for (int nt = 0; nt < 4; nt++) {
        int colw = nq * 32 + nt * 8 + 2 * (lane & 3);
        int r0 = mg * 16 + (lane >> 2);
        *reinterpret_cast<float2*>(&s.hbuf[r0][colw]) = make_float2(acc[nt][0], acc[nt][1]);
        *reinterpret_cast<float2*>(&s.hbuf[r0 + 8][colw]) = make_float2(acc[nt][2], acc[nt][3]);
    }
    __syncthreads();

    // epilogue: + bias + PE, rmsnorm, write g_h / g_scale / g_nh
    {
        int row = t >> 3, part = t & 7;
        int grow = growb + row, bb = grow / 125, kq = grow - bb * 125;
        float ssq = 0.f;
#pragma unroll
        for (int j = 0; j < 16; j++) {
            int c = part * 16 + j;
            float v = s.hbuf[row][c] + peb[c] + g_pe[kq * 128 + c];
            s.hbuf[row][c] = v;
            ssq += v * v;
        }
        ssq += __shfl_xor_sync(0xffffffffu, ssq, 1);
        ssq += __shfl_xor_sync(0xffffffffu, ssq, 2);
        ssq += __shfl_xor_sync(0xffffffffu, ssq, 4);
        float sc = rsqrtf(ssq * (1.0f / 128.0f) + EPS_);
        if (part == 0) g_scale[grow] = sc;
#pragma unroll
        for (int j = 0; j < 16; j += 2) {
            int c = part * 16 + j;
            float v0 = s.hbuf[row][c], v1 = s.hbuf[row][c + 1];
            *reinterpret_cast<float2*>(&g_h[grow * 128 + c]) = make_float2(v0, v1);
            bf h0, l0, h1, l1;
            split_bf(v0 * sc, h0, l0); split_bf(v1 * sc, h1, l1);
            bf hp[2] = {h0, h1}, lp[2] = {l0, l1};
            *reinterpret_cast<unsigned*>(&g_nhh[grow * 128 + c]) = *reinterpret_cast<unsigned*>(hp);
            *reinterpret_cast<unsigned*>(&g_nhl[grow * 128 + c]) = *reinterpret_cast<unsigned*>(lp);
        }
    }
}

// =====================================================================
// Kernel 2: in-projections (bf16-split MMA). A = g_nh (pre-normalized,
// bf16 hi/lo), W = prepped (nw folded). grid (125, 4): ny 0,1 -> a;
// 2,3 -> b. K=128 in 4 chunks. Direct fragment epilogue (fp32 out).
// =====================================================================
__global__ __launch_bounds__(256) void k_inproj(int lbase) {
    __shared__ __align__(16) struct { bf ah[32][40], al[32][40], wh[128][40], wl[128][40]; } s;
    const int t = threadIdx.x, lane = t & 31, w = t >> 5;
    const int mg = w >> 2, nq = w & 3;
    const int growb = blockIdx.x * 32;
    const int ny = blockIdx.y;
    const int woff = lbase + ny * 128 * 128;

    float acc[4][4] = {};

    for (int kch = 0; kch < 4; kch++) {
        // stage A (bf16 copy via cp.async): 128 chunks per slab
        {
            int half = t >> 7;          // 0: hi, 1: lo
            int idx = t & 127;
            int row = idx >> 2, k4 = idx & 3;
            const bf* srcb = (half ? g_nhl : g_nhh) + (growb + row) * 128 + kch * 32 + k4 * 8;
            bf* dst = half ? &s.al[row][k4 * 8] : &s.ah[row][k4 * 8];
            cp16((unsigned)__cvta_generic_to_shared(dst), srcb);
        }
        // stage W
#pragma unroll
        for (int q = 0; q < 2; q++) {
            int idx = t + 256 * q;
            int row = idx >> 2, k4 = idx & 3;
            cp16((unsigned)__cvta_generic_to_shared(&s.wh[row][k4 * 8]),
                 g_wbh + woff + row * 128 + kch * 32 + k4 * 8);
            cp16((unsigned)__cvta_generic_to_shared(&s.wl[row][k4 * 8]),
                 g_wbl + woff + row * 128 + kch * 32 + k4 * 8);
        }
        cp_commit(); cp_waitall();
        __syncthreads();

#pragma unroll
        for (int kst = 0; kst < 2; kst++) {
            const int ko = kst * 16 + 2 * (lane & 3);
            const int r0 = mg * 16 + (lane >> 2);
            unsigned ah[4], al_[4];
            ah[0] = ldu32(&s.ah[r0][ko]);     ah[1] = ldu32(&s.ah[r0 + 8][ko]);
            ah[2] = ldu32(&s.ah[r0][ko + 8]); ah[3] = ldu32(&s.ah[r0 + 8][ko + 8]);
            al_[0] = ldu32(&s.al[r0][ko]);     al_[1] = ldu32(&s.al[r0 + 8][ko]);
            al_[2] = ldu32(&s.al[r0][ko + 8]); al_[3] = ldu32(&s.al[r0 + 8][ko + 8]);
#pragma unroll
            for (int nt = 0; nt < 4; nt++) {
                int n = nq * 32 + nt * 8 + (lane >> 2);
                unsigned bh0 = ldu32(&s.wh[n][ko]), bh1 = ldu32(&s.wh[n][ko + 8]);
                unsigned bl0 = ldu32(&s.wl[n][ko]), bl1 = ldu32(&s.wl[n][ko + 8]);
                mma_bf16(acc[nt], ah, bh0, bh1);
                mma_bf16(acc[nt], ah, bl0, bl1);
                mma_bf16(acc[nt], al_, bh0, bh1);
            }
        }
        __syncthreads();
    }

    float* out = (ny < 2) ? g_a : g_bv;
    const int colb = (ny & 1) * 128;
#pragma unroll
    for (int nt = 0; nt < 4; nt++) {
        int col = colb + nq * 32 + nt * 8 + 2 * (lane & 3);
        int r0 = growb + mg * 16 + (lane >> 2);
        *reinterpret_cast<float2*>(&out[r0 * INNER_ + col]) = make_float2(acc[nt][0], acc[nt][1]);
        *reinterpret_cast<float2*>(&out[(r0 + 8) * INNER_ + col]) = make_float2(acc[nt][2], acc[nt][3]);
    }
}

// =====================================================================
// Kernel 3: conv + silu + chunked parallel scan + b-gate (unchanged).
// =====================================================================
__global__ __launch_bounds__(800) void k_convscan(const float* __restrict__ cw,
                                                  const float* __restrict__ cb,
                                                  const float* __restrict__ al,
                                                  const float* __restrict__ be,
                                                  const float* __restrict__ ga,
                                                  const float* __restrict__ de) {
    __shared__ float ends[25][32];
    const int t = threadIdx.x;
    const int ch = t & 31, ck = t >> 5;
    const int b = blockIdx.x >> 3;
    const int ig = blockIdx.x & 7;
    const int i = ig * 32 + ch;
    const int base = b * 125 * INNER_ + i;
    const int k0 = ck * 5;

    const float* w = cw + i * 5;
    const float w0 = w[0], w1 = w[1], w2 = w[2], w3 = w[3], w4 = w[4];
    const float bias = cb[i];
    const float siga = 1.f / (1.f + __expf(-al[i]));
    const float bb = be[i], gg = ga[i], dd = de[i];

    float av[9];
#pragma unroll
    for (int q = 0; q < 9; q++) {
        int kk = k0 - 2 + q;
        av[q] = (kk >= 0 && kk <= 124) ? g_a[base + kk * INNER_] : 0.f;
    }

    float tv[5];
    float s = 0.f;
#pragma unroll
    for (int q = 0; q < 5; q++) {
        float acc = bias;
        acc = fmaf(w0, av[q], acc);
        acc = fmaf(w1, av[q + 1], acc);
        acc = fmaf(w2, av[q + 2], acc);
        acc = fmaf(w3, av[q + 3], acc);
        acc = fmaf(w4, av[q + 4], acc);
        float u = acc / (1.f + __expf(-acc));
        s = fmaf(siga, s, bb * u);
        tv[q] = fmaf(gg, s, dd * u);
    }
    ends[ck][ch] = s;
    __syncthreads();

    float p2 = siga * siga, p4 = p2 * p2;
    float a5 = p4 * siga;
    float st = 0.f;
    for (int jj = 0; jj < ck; jj++)
        st = fmaf(a5, st, ends[jj][ch]);
    float gc = gg * st;

    float pw = siga;
#pragma unroll
    for (int q = 0; q < 5; q++) {
        float bv = g_bv[base + (k0 + q) * INNER_];
        g_u[base + (k0 + q) * INNER_] = fmaf(gc, pw, tv[q]) * bv;
        pw *= siga;
    }
}

// =====================================================================
// Kernel 4: out-projection (bf16-split MMA) + DOUBLED residual
// (h <- 2h + y) + rmsnorm epilogue -> g_h, g_scale, g_nh. K=256 in 8
// chunks; A from g_u (fp32 -> split at staging).
// =====================================================================
__global__ __launch_bounds__(256) void k_outproj(int woff) {
    __shared__ __align__(16) union {
        struct { bf ah[32][40], al[32][40], wh[128][40], wl[128][40]; } m;
        float hbuf[32][132];
    } s;
    const int t = threadIdx.x, lane = t & 31, w = t >> 5;
    const int mg = w >> 2, nq = w & 3;
    const int growb = blockIdx.x * 32;

    float acc[4][4] = {};

    for (int kch = 0; kch < 8; kch++) {
        // stage A: fp32 g_u -> split
        {
            int row = t >> 3, f4 = t & 7;
            float4 v = *reinterpret_cast<const float4*>(
                &g_u[(growb + row) * INNER_ + kch * 32 + f4 * 4]);
            bf h[4], l[4];
            split_bf(v.x, h[0], l[0]); split_bf(v.y, h[1], l[1]);
            split_bf(v.z, h[2], l[2]); split_bf(v.w, h[3], l[3]);
            *reinterpret_cast<ull*>(&s.m.ah[row][f4 * 4]) = *reinterpret_cast<ull*>(h);
            *reinterpret_cast<ull*>(&s.m.al[row][f4 * 4]) = *reinterpret_cast<ull*>(l);
        }
        // stage W
#pragma unroll
        for (int q = 0; q < 2; q++) {
            int idx = t + 256 * q;
            int row = idx >> 2, k4 = idx & 3;
            cp16((unsigned)__cvta_generic_to_shared(&s.m.wh[row][k4 * 8]),
                 g_wbh + woff + row * 256 + kch * 32 + k4 * 8);
            cp16((unsigned)__cvta_generic_to_shared(&s.m.wl[row][k4 * 8]),
                 g_wbl + woff + row * 256 + kch * 32 + k4 * 8);
        }
        cp_commit(); cp_waitall();
        __syncthreads();

#pragma unroll
        for (int kst = 0; kst < 2; kst++) {
            const int ko = kst * 16 + 2 * (lane & 3);
            const int r0 = mg * 16 + (lane >> 2);
            unsigned ah[4], al_[4];
            ah[0] = ldu32(&s.m.ah[r0][ko]);     ah[1] = ldu32(&s.m.ah[r0 + 8][ko]);
            ah[2] = ldu32(&s.m.ah[r0][ko + 8]); ah[3] = ldu32(&s.m.ah[r0 + 8][ko + 8]);
            al_[0] = ldu32(&s.m.al[r0][ko]);     al_[1] = ldu32(&s.m.al[r0 + 8][ko]);
            al_[2] = ldu32(&s.m.al[r0][ko + 8]); al_[3] = ldu32(&s.m.al[r0 + 8][ko + 8]);
#pragma unroll
            for (int nt = 0; nt < 4; nt++) {
                int n = nq * 32 + nt * 8 + (lane >> 2);
                unsigned bh0 = ldu32(&s.m.wh[n][ko]), bh1 = ldu32(&s.m.wh[n][ko + 8]);
                unsigned bl0 = ldu32(&s.m.wl[n][ko]), bl1 = ldu32(&s.m.wl[n][ko + 8]);
                mma_bf16(acc[nt], ah, bh0, bh1);
                mma_bf16(acc[nt], ah, bl0, bl1);
                mma_bf16(acc[nt], al_, bh0, bh1);
            }
        }
        __syncthreads();
    }

    // frags -> hbuf
#pragma unroll
    for (int nt = 0; nt < 4; nt++) {
        int colw = nq * 32 + nt * 8 + 2 * (lane & 3);
        int r0 = mg * 16 + (lane >> 2);
        *reinterpret_cast<float2*>(&s.hbuf[r0][colw]) = make_float2(acc[nt][0], acc[nt][1]);
        *reinterpret_cast<float2*>(&s.hbuf[r0 + 8][colw]) = make_float2(acc[nt][2], acc[nt][3]);
    }
    __syncthreads();

    // epilogue: nv = 2h + y; rmsnorm; write g_h, g_scale, g_nh
    {
        int row = t >> 3, part = t & 7;
        int grow = growb + row;
        float ssq = 0.f;
#pragma unroll
        for (int j = 0; j < 16; j++) {
            int c = part * 16 + j;
            float nv = 2.f * g_h[grow * 128 + c] + s.hbuf[row][c];
            s.hbuf[row][c] = nv;
            ssq += nv * nv;
        }
        ssq += __shfl_xor_sync(0xffffffffu, ssq, 1);
        ssq += __shfl_xor_sync(0xffffffffu, ssq, 2);
        ssq += __shfl_xor_sync(0xffffffffu, ssq, 4);
        float sc = rsqrtf(ssq * (1.0f / 128.0f) + EPS_);
        if (part == 0) g_scale[grow] = sc;
#pragma unroll
        for (int j = 0; j < 16; j += 2) {
            int c = part * 16 + j;
            float v0 = s.hbuf[row][c], v1 = s.hbuf[row][c + 1];
            *reinterpret_cast<float2*>(&g_h[grow * 128 + c]) = make_float2(v0, v1);
            bf h0, l0, h1, l1;
            split_bf(v0 * sc, h0, l0); split_bf(v1 * sc, h1, l1);
            bf hp[2] = {h0, h1}, lp[2] = {l0, l1};
            *reinterpret_cast<unsigned*>(&g_nhh[grow * 128 + c]) = *reinterpret_cast<unsigned*>(hp);
            *reinterpret_cast<unsigned*>(&g_nhl[grow * 128 + c]) = *reinterpret_cast<unsigned*>(lp);
        }
    }
}

// =====================================================================
// Kernel 5a: normalized flat activations -> bf16 hi/lo split slabs
// =====================================================================
__global__ __launch_bounds__(256) void k_flatcvt(const float* __restrict__ nfw) {
    int idx = blockIdx.x * 256 + threadIdx.x;   // grid 500
    float sc = g_scale[idx >> 5];
    int j4 = idx << 2;
    float4 h = *reinterpret_cast<const float4*>(&g_h[j4]);
    float4 nv = *reinterpret_cast<const float4*>(&nfw[j4 & 127]);
    float vv[4] = {h.x * sc * nv.x, h.y * sc * nv.y, h.z * sc * nv.z, h.w * sc * nv.w};
    bf hv[4], lv[4];
#pragma unroll
    for (int j = 0; j < 4; j++) split_bf(vv[j], hv[j], lv[j]);
    *reinterpret_cast<ull*>(&g_fhi[j4]) = *reinterpret_cast<ull*>(hv);
    *reinterpret_cast<ull*>(&g_flo[j4]) = *reinterpret_cast<ull*>(lv);
}

// =====================================================================
// Kernel 5b: final GEMM via bf16 hi/lo split tensor MMA (unchanged R7).
// =====================================================================
__global__ __launch_bounds__(256) void k_final(const float* __restrict__ outW) {
    __shared__ __align__(16) bf fh[32][328];
    __shared__ __align__(16) bf fl[32][328];

    const int t = threadIdx.x;
    const int w = t >> 5, l = t & 31;
    const int g = l >> 2, tig = l & 3;
    const int obase = blockIdx.x * 128;
    const int ks = blockIdx.y;
    const int jbase = ks * 320;

    {
        unsigned fhb = (unsigned)__cvta_generic_to_shared(&fh[0][0]);
        unsigned flb = (unsigned)__cvta_generic_to_shared(&fl[0][0]);
#pragma unroll
        for (int q = 0; q < 5; q++) {
            int c = t + 256 * q;
            int b = c / 40, kc = c - b * 40;
            cp16(fhb + b * 656 + kc * 16, g_fhi + b * DNP_ + jbase + kc * 8);
            cp16(flb + b * 656 + kc * 16, g_flo + b * DNP_ + jbase + kc * 8);
        }
    }
    cp_commit();

    const int n0 = obase + w * 16 + g;
    const float* w0p = outW + (size_t)n0 * DNP_ + jbase + 2 * tig;
    const float* w1p = w0p + (size_t)8 * DNP_;

    float c[2][2][4];
#pragma unroll
    for (int mt = 0; mt < 2; mt++)
#pragma unroll
        for (int nt = 0; nt < 2; nt++)
#pragma unroll
            for (int q = 0; q < 4; q++) c[mt][nt][q] = 0.f;

    float2 cur[4] = { *reinterpret_cast<const float2*>(w0p),
                      *reinterpret_cast<const float2*>(w0p + 8),
                      *reinterpret_cast<const float2*>(w1p),
                      *reinterpret_cast<const float2*>(w1p + 8) };

    cp_waitall();
    __syncthreads();

    for (int ch = 0; ch < 20; ch++) {
        int chn = (ch + 1 < 20) ? (ch + 1) : 19;
        float2 nxt[4] = { *reinterpret_cast<const float2*>(w0p + chn * 16),
                          *reinterpret_cast<const float2*>(w0p + chn * 16 + 8),
                          *reinterpret_cast<const float2*>(w1p + chn * 16),
                          *reinterpret_cast<const float2*>(w1p + chn * 16 + 8) };

        const int off = ch * 16 + 2 * tig;
        unsigned ahi[2][4], alo[2][4];
#pragma unroll
        for (int mt = 0; mt < 2; mt++) {
            int r = g + mt * 16;
            ahi[mt][0] = ldu32(&fh[r][off]);
            ahi[mt][1] = ldu32(&fh[r + 8][off]);
            ahi[mt][2] = ldu32(&fh[r][off + 8]);
            ahi[mt][3] = ldu32(&fh[r + 8][off + 8]);
            alo[mt][0] = ldu32(&fl[r][off]);
            alo[mt][1] = ldu32(&fl[r + 8][off]);
            alo[mt][2] = ldu32(&fl[r][off + 8]);
            alo[mt][3] = ldu32(&fl[r + 8][off + 8]);
        }

        unsigned bhi[2][2], blo[2][2];
#pragma unroll
        for (int nt = 0; nt < 2; nt++) {
#pragma unroll
            for (int hb = 0; hb < 2; hb++) {
                float2 wv = cur[nt * 2 + hb];
                __nv_bfloat162 h2 = __floats2bfloat162_rn(wv.x, wv.y);
                float2 lo2 = make_float2(wv.x - __bfloat162float(__low2bfloat16(h2)),
                                         wv.y - __bfloat162float(__high2bfloat16(h2)));
                __nv_bfloat162 l2 = __floats2bfloat162_rn(lo2.x, lo2.y);
                bhi[nt][hb] = *reinterpret_cast<unsigned*>(&h2);
                blo[nt][hb] = *reinterpret_cast<unsigned*>(&l2);
            }
        }

#pragma unroll
        for (int mt = 0; mt < 2; mt++)
#pragma unroll
            for (int nt = 0; nt < 2; nt++) {
                mma_bf16(c[mt][nt], ahi[mt], bhi[nt][0], bhi[nt][1]);
                mma_bf16(c[mt][nt], ahi[mt], blo[nt][0], blo[nt][1]);
                mma_bf16(c[mt][nt], alo[mt], bhi[nt][0], bhi[nt][1]);
            }

#pragma unroll
        for (int q = 0; q < 4; q++) cur[q] = nxt[q];
    }

#pragma unroll
    for (int mt = 0; mt < 2; mt++)
#pragma unroll
        for (int nt = 0; nt < 2; nt++) {
            int o = obase + w * 16 + nt * 8 + 2 * tig;
            int b0 = g + mt * 16;
            float* p0 = &g_part[(ks * B_ + b0) * CF_ + o];
            float* p1 = &g_part[(ks * B_ + b0 + 8) * CF_ + o];
            *reinterpret_cast<float2*>(p0) = make_float2(c[mt][nt][0], c[mt][nt][1]);
            *reinterpret_cast<float2*>(p1) = make_float2(c[mt][nt][2], c[mt][nt][3]);
        }
}

// Kernel 6: reduce split-K partials + bias -> d_out (deterministic)
__global__ __launch_bounds__(256) void k_reduce(const float* __restrict__ outb,
                                                float* __restrict__ out) {
    int idx = blockIdx.x * 256 + threadIdx.x;
    int b = idx / CF_, o = idx - b * CF_;
    float v = outb[o];
#pragma unroll
    for (int s = 0; s < KS_; s++) v += g_part[(s * B_ + b) * CF_ + o];
    out[idx] = v;
}

// =====================================================================
extern "C" void kernel_launch(void* const* d_in, const int* in_sizes, int n_in,
                              void* d_out, int out_size) {
    const float* x     = (const float*)d_in[0];
    const float* peW   = (const float*)d_in[1];
    const float* peb   = (const float*)d_in[2];
    const float* normw = (const float*)d_in[3];
    const float* ipaW  = (const float*)d_in[4];
    const float* ipbW  = (const float*)d_in[5];
    const float* convW = (const float*)d_in[6];
    const float* convb = (const float*)d_in[7];
    const float* alp   = (const float*)d_in[8];
    const float* bet   = (const float*)d_in[9];
    const float* gam   = (const float*)d_in[10];
    const float* del   = (const float*)d_in[11];
    const float* opW   = (const float*)d_in[12];
    const float* normf = (const float*)d_in[13];
    const float* outW  = (const float*)d_in[14];
    const float* outb  = (const float*)d_in[15];
    float* out = (float*)d_out;

    k_pe<<<NP_, 128>>>();
    // weight prep: embed + per-layer (ipa, ipb with nw folded; op plain)
    k_prepw<<<WSZ_EMB / 256, 256>>>(peW, nullptr, WOFF_EMB, 0);
    for (int l = 0; l < 4; l++) {
        int lb = WSZ_EMB + l * WSZ_LAYER;
        k_prepw<<<128, 256>>>(ipaW + l * 256 * 128, normw + l * 128, lb, 127);
        k_prepw<<<128, 256>>>(ipbW + l * 256 * 128, normw + l * 128, lb + 32768, 127);
        k_prepw<<<128, 256>>>(opW + l * 128 * 256, nullptr, lb + 65536, 0);
    }

    k_embed<<<M_ / 32, 256>>>(x, peb);
    for (int l = 0; l < 4; l++) {
        int lb = WSZ_EMB + l * WSZ_LAYER;
        k_inproj<<<dim3(M_ / 32, 4), 256>>>(lb);
        k_convscan<<<B_ * 8, 800>>>(convW + l * INNER_ * 5, convb + l * INNER_,
                                    alp + l * INNER_, bet + l * INNER_,
                                    gam + l * INNER_, del + l * INNER_);
        k_outproj<<<M_ / 32, 256>>>(lb + 65536);
    }
    k_flatcvt<<<500, 256>>>(normf);
    k_final<<<dim3(CF_ / 128, KS_), 256>>>(outW);
    k_reduce<<<(B_ * CF_) / 256, 256>>>(outb, out);
}

// round 9
// speedup vs baseline: 3.1269x; 1.0192x over previous
#include <cuda_runtime.h>
#include <cuda_bf16.h>
#include <math.h>

using ull = unsigned long long;
using bf = __nv_bfloat16;

constexpr int B_   = 32;
constexpr int C_   = 64;
constexpr int L_   = 512;
constexpr int NP_  = 125;
constexpr int D_   = 128;
constexpr int INNER_ = 256;
constexpr int M_   = B_ * NP_;    // 4000
constexpr int CF_  = 6144;        // C*F
constexpr int DNP_ = 16000;       // D*NP
constexpr int KS_  = 50;          // split-K for final GEMM (320 k each)
constexpr float EPS_ = 1e-5f;

// weight slab offsets (bf16 hi/lo converted once per launch)
constexpr int WOFF_EMB = 0;                 // 128 x 1024
constexpr int WSZ_EMB  = 128 * 1024;
constexpr int WSZ_LAYER = 2 * 256 * 128 + 128 * 256;  // ipa+ipb + op = 98304
constexpr int WTOT = WSZ_EMB + 4 * WSZ_LAYER;         // 524288
constexpr int PREP_TOT = WTOT + NP_ * D_;             // + PE table

// -------- device scratch (no allocation allowed) --------
__device__ float g_h[M_ * D_];          // hidden (fp32, residual base)
__device__ float g_scale[M_];           // rmsnorm scale per row (final norm)
__device__ float g_a[M_ * INNER_];      // in-proj a
__device__ float g_bv[M_ * INNER_];     // in-proj b
__device__ float g_u[M_ * INNER_];      // gated scan out
__device__ float g_part[KS_ * B_ * CF_];// split-K partials
__device__ float g_pe[NP_ * D_];        // accurate sincos PE table
__device__ bf g_fhi[B_ * DNP_];         // normalized flat, bf16 hi
__device__ bf g_flo[B_ * DNP_];         // normalized flat, bf16 lo
__device__ bf g_nhh[M_ * D_];           // normalized hidden, bf16 hi
__device__ bf g_nhl[M_ * D_];           // normalized hidden, bf16 lo
__device__ bf g_wbh[WTOT];              // weights bf16 hi
__device__ bf g_wbl[WTOT];              // weights bf16 lo

__device__ __forceinline__ void cp16(unsigned s, const void* g) {
    asm volatile("cp.async.cg.shared.global [%0],[%1],16;" :: "r"(s), "l"(g));
}
__device__ __forceinline__ void cp_commit() { asm volatile("cp.async.commit_group;"); }
__device__ __forceinline__ void cp_waitall() { asm volatile("cp.async.wait_group 0;" ::: "memory"); }

// bf16 mma m16n8k16 row.col f32 accumulate
__device__ __forceinline__ void mma_bf16(float* c, const unsigned* a,
                                         unsigned b0, unsigned b1) {
    asm volatile(
        "mma.sync.aligned.m16n8k16.row.col.f32.bf16.bf16.f32 "
        "{%0,%1,%2,%3}, {%4,%5,%6,%7}, {%8,%9}, {%0,%1,%2,%3};"
        : "+f"(c[0]), "+f"(c[1]), "+f"(c[2]), "+f"(c[3])
        : "r"(a[0]), "r"(a[1]), "r"(a[2]), "r"(a[3]), "r"(b0), "r"(b1));
}
__device__ __forceinline__ unsigned ldu32(const bf* p) {
    return *reinterpret_cast<const unsigned*>(p);
}
__device__ __forceinline__ void split_bf(float v, bf& h, bf& l) {
    h = __float2bfloat16(v);
    l = __float2bfloat16(v - __bfloat162float(h));
}

// =====================================================================
// Kernel 0: MERGED prep — all weight slabs (bf16 hi/lo) + PE table in
// one launch (was 13 tiny launches + k_pe = ~57us of launch overhead).
// =====================================================================
__global__ __launch_bounds__(256) void k_prep_all(const float* __restrict__ peW,
                                                  const float* __restrict__ normw,
                                                  const float* __restrict__ ipaW,
                                                  const float* __restrict__ ipbW,
                                                  const float* __restrict__ opW) {
    int idx = blockIdx.x * 256 + threadIdx.x;
    if (idx >= PREP_TOT) return;
    if (idx >= WTOT) {
        // PE table region
        int p = idx - WTOT;
        int kq = p >> 7, col = p & 127;
        int ii = col >> 1;
        float targ = (-9.210340371976184f) * (float)ii * (1.0f / 64.0f);
        float divf = (float)exp((double)targ);
        float ang = (float)kq * divf;
        double a = (double)ang;
        g_pe[p] = (float)((col & 1) ? cos(a) : sin(a));
        return;
    }
    float v;
    if (idx < WSZ_EMB) {
        v = peW[idx];
    } else {
        int r = idx - WSZ_EMB;
        int l = r / WSZ_LAYER;
        int o = r - l * WSZ_LAYER;
        if (o < 32768)       v = ipaW[l * 32768 + o] * normw[l * 128 + (o & 127)];
        else if (o < 65536)  v = ipbW[l * 32768 + (o - 32768)] * normw[l * 128 + (o & 127)];
        else                 v = opW[l * 32768 + (o - 65536)];
    }
    bf h, l2; split_bf(v, h, l2);
    g_wbh[idx] = h;
    g_wbl[idx] = l2;
}

// =====================================================================
// Kernel 1: patch-embed GEMM (bf16-split MMA) + bias + PE; epilogue
// writes g_h, g_scale, g_nhh/g_nhl.
// =====================================================================
__global__ __launch_bounds__(256) void k_embed(const float* __restrict__ x,
                                               const float* __restrict__ peb) {
    __shared__ __align__(16) union {
        struct { bf ah[32][40], al[32][40], wh[128][40], wl[128][40]; } m;
        float hbuf[32][132];
    } s;
    const int t = threadIdx.x, lane = t & 31, w = t >> 5;
    const int mg = w >> 2, nq = w & 3;
    const int growb = blockIdx.x * 32;

    float acc[4][4] = {};

    for (int kch = 0; kch < 32; kch++) {
#pragma unroll
        for (int q = 0; q < 4; q++) {
            int idx = t + 256 * q;
            int row = idx >> 5, kk = idx & 31;
            int gk = kch * 32 + kk, c = gk >> 4, p = gk & 15;
            int grow = growb + row, bb = grow / 125, kq = grow - bb * 125;
            float v = x[(bb * C_ + c) * L_ + kq * 4 + p];
            split_bf(v, s.m.ah[row][kk], s.m.al[row][kk]);
        }
#pragma unroll
        for (int q = 0; q < 2; q++) {
            int idx = t + 256 * q;
            int row = idx >> 2, k4 = idx & 3;
            const bf* sh = g_wbh + WOFF_EMB + row * 1024 + kch * 32 + k4 * 8;
            const bf* sl = g_wbl + WOFF_EMB + row * 1024 + kch * 32 + k4 * 8;
            cp16((unsigned)__cvta_generic_to_shared(&s.m.wh[row][k4 * 8]), sh);
            cp16((unsigned)__cvta_generic_to_shared(&s.m.wl[row][k4 * 8]), sl);
        }
        cp_commit(); cp_waitall();
        __syncthreads();

#pragma unroll
        for (int kst = 0; kst < 2; kst++) {
            const int ko = kst * 16 + 2 * (lane & 3);
            const int r0 = mg * 16 + (lane >> 2);
            unsigned ah[4], al_[4];
            ah[0] = ldu32(&s.m.ah[r0][ko]);     ah[1] = ldu32(&s.m.ah[r0 + 8][ko]);
            ah[2] = ldu32(&s.m.ah[r0][ko + 8]); ah[3] = ldu32(&s.m.ah[r0 + 8][ko + 8]);
            al_[0] = ldu32(&s.m.al[r0][ko]);     al_[1] = ldu32(&s.m.al[r0 + 8][ko]);
            al_[2] = ldu32(&s.m.al[r0][ko + 8]); al_[3] = ldu32(&s.m.al[r0 + 8][ko + 8]);
#pragma unroll
            for (int nt = 0; nt < 4; nt++) {
                int n = nq * 32 + nt * 8 + (lane >> 2);
                unsigned bh0 = ldu32(&s.m.wh[n][ko]), bh1 = ldu32(&s.m.wh[n][ko + 8]);
                unsigned bl0 = ldu32(&s.m.wl[n][ko]), bl1 = ldu32(&s.m.wl[n][ko + 8]);
                mma_bf16(acc[nt], ah, bh0, bh1);
                mma_bf16(acc[nt], ah, bl0, bl1);
                mma_bf16(acc[nt], al_, bh0, bh1);
            }
        }
        __syncthreads();
    }

#pragma unroll
    for (int nt = 0; nt < 4; nt++) {
        int colw = nq * 32 + nt * 8 + 2 * (lane & 3);
        int r0 = mg * 16 + (lane >> 2);
        *reinterpret_cast<float2*>(&s.hbuf[r0][colw]) = make_float2(acc[nt][0], acc[nt][1]);
        *reinterpret_cast<float2*>(&s.hbuf[r0 + 8][colw]) = make_float2(acc[nt][2], acc[nt][3]);
    }
    __syncthreads();

    {
        int row = t >> 3, part = t & 7;
        int grow = growb + row, bb = grow / 125, kq = grow - bb * 125;
        float ssq = 0.f;
#pragma unroll
        for (int j = 0; j < 16; j++) {
            int c = part * 16 + j;
            float v = s.hbuf[row][c] + peb[c] + g_pe[kq * 128 + c];
            s.hbuf[row][c] = v;
            ssq += v * v;
        }
        ssq += __shfl_xor_sync(0xffffffffu, ssq, 1);
        ssq += __shfl_xor_sync(0xffffffffu, ssq, 2);
        ssq += __shfl_xor_sync(0xffffffffu, ssq, 4);
        float sc = rsqrtf(ssq * (1.0f / 128.0f) + EPS_);
        if (part == 0) g_scale[grow] = sc;
#pragma unroll
        for (int j = 0; j < 16; j += 2) {
            int c = part * 16 + j;
            float v0 = s.hbuf[row][c], v1 = s.hbuf[row][c + 1];
            *reinterpret_cast<float2*>(&g_h[grow * 128 + c]) = make_float2(v0, v1);
            bf h0, l0, h1, l1;
            split_bf(v0 * sc, h0, l0); split_bf(v1 * sc, h1, l1);
            bf hp[2] = {h0, h1}, lp[2] = {l0, l1};
            *reinterpret_cast<unsigned*>(&g_nhh[grow * 128 + c]) = *reinterpret_cast<unsigned*>(hp);
            *reinterpret_cast<unsigned*>(&g_nhl[grow * 128 + c]) = *reinterpret_cast<unsigned*>(lp);
        }
    }
}

// =====================================================================
// Kernel 2: in-projections (bf16-split MMA).
// =====================================================================
__global__ __launch_bounds__(256) void k_inproj(int lbase) {
    __shared__ __align__(16) struct { bf ah[32][40], al[32][40], wh[128][40], wl[128][40]; } s;
    const int t = threadIdx.x, lane = t & 31, w = t >> 5;
    const int mg = w >> 2, nq = w & 3;
    const int growb = blockIdx.x * 32;
    const int ny = blockIdx.y;
    const int woff = lbase + ny * 128 * 128;

    float acc[4][4] = {};

    for (int kch = 0; kch < 4; kch++) {
        {
            int half = t >> 7;
            int idx = t & 127;
            int row = idx >> 2, k4 = idx & 3;
            const bf* srcb = (half ? g_nhl : g_nhh) + (growb + row) * 128 + kch * 32 + k4 * 8;
            bf* dst = half ? &s.al[row][k4 * 8] : &s.ah[row][k4 * 8];
            cp16((unsigned)__cvta_generic_to_shared(dst), srcb);
        }
#pragma unroll
        for (int q = 0; q < 2; q++) {
            int idx = t + 256 * q;
            int row = idx >> 2, k4 = idx & 3;
            cp16((unsigned)__cvta_generic_to_shared(&s.wh[row][k4 * 8]),
                 g_wbh + woff + row * 128 + kch * 32 + k4 * 8);
            cp16((unsigned)__cvta_generic_to_shared(&s.wl[row][k4 * 8]),
                 g_wbl + woff + row * 128 + kch * 32 + k4 * 8);
        }
        cp_commit(); cp_waitall();
        __syncthreads();

#pragma unroll
        for (int kst = 0; kst < 2; kst++) {
            const int ko = kst * 16 + 2 * (lane & 3);
            const int r0 = mg * 16 + (lane >> 2);
            unsigned ah[4], al_[4];
            ah[0] = ldu32(&s.ah[r0][ko]);     ah[1] = ldu32(&s.ah[r0 + 8][ko]);
            ah[2] = ldu32(&s.ah[r0][ko + 8]); ah[3] = ldu32(&s.ah[r0 + 8][ko + 8]);
            al_[0] = ldu32(&s.al[r0][ko]);     al_[1] = ldu32(&s.al[r0 + 8][ko]);
            al_[2] = ldu32(&s.al[r0][ko + 8]); al_[3] = ldu32(&s.al[r0 + 8][ko + 8]);
#pragma unroll
            for (int nt = 0; nt < 4; nt++) {
                int n = nq * 32 + nt * 8 + (lane >> 2);
                unsigned bh0 = ldu32(&s.wh[n][ko]), bh1 = ldu32(&s.wh[n][ko + 8]);
                unsigned bl0 = ldu32(&s.wl[n][ko]), bl1 = ldu32(&s.wl[n][ko + 8]);
                mma_bf16(acc[nt], ah, bh0, bh1);
                mma_bf16(acc[nt], ah, bl0, bl1);
                mma_bf16(acc[nt], al_, bh0, bh1);
            }
        }
        __syncthreads();
    }

    float* out = (ny < 2) ? g_a : g_bv;
    const int colb = (ny & 1) * 128;
#pragma unroll
    for (int nt = 0; nt < 4; nt++) {
        int col = colb + nq * 32 + nt * 8 + 2 * (lane & 3);
        int r0 = growb + mg * 16 + (lane >> 2);
        *reinterpret_cast<float2*>(&out[r0 * INNER_ + col]) = make_float2(acc[nt][0], acc[nt][1]);
        *reinterpret_cast<float2*>(&out[(r0 + 8) * INNER_ + col]) = make_float2(acc[nt][2], acc[nt][3]);
    }
}

// =====================================================================
// Kernel 3: conv + silu + chunked parallel scan + b-gate.
// bv loads hoisted above the barrier to overlap with conv/scan compute.
// =====================================================================
__global__ __launch_bounds__(800) void k_convscan(const float* __restrict__ cw,
                                                  const float* __restrict__ cb,
                                                  const float* __restrict__ al,
                                                  const float* __restrict__ be,
                                                  const float* __restrict__ ga,
                                                  const float* __restrict__ de) {
    __shared__ float ends[25][32];
    const int t = threadIdx.x;
    const int ch = t & 31, ck = t >> 5;
    const int b = blockIdx.x >> 3;
    const int ig = blockIdx.x & 7;
    const int i = ig * 32 + ch;
    const int base = b * 125 * INNER_ + i;
    const int k0 = ck * 5;

    const float* w = cw + i * 5;
    const float w0 = w[0], w1 = w[1], w2 = w[2], w3 = w[3], w4 = w[4];
    const float bias = cb[i];
    const float siga = 1.f / (1.f + __expf(-al[i]));
    const float bb = be[i], gg = ga[i], dd = de[i];

    float av[9];
#pragma unroll
    for (int q = 0; q < 9; q++) {
        int kk = k0 - 2 + q;
        av[q] = (kk >= 0 && kk <= 124) ? g_a[base + kk * INNER_] : 0.f;
    }
    // hoisted b-gate loads (latency hidden behind conv/scan + barrier)
    float bvv[5];
#pragma unroll
    for (int q = 0; q < 5; q++) bvv[q] = g_bv[base + (k0 + q) * INNER_];

    float tv[5];
    float s = 0.f;
#pragma unroll
    for (int q = 0; q < 5; q++) {
        float acc = bias;
        acc = fmaf(w0, av[q], acc);
        acc = fmaf(w1, av[q + 1], acc);
        acc = fmaf(w2, av[q + 2], acc);
        acc = fmaf(w3, av[q + 3], acc);
        acc = fmaf(w4, av[q + 4], acc);
        float u = acc / (1.f + __expf(-acc));
        s = fmaf(siga, s, bb * u);
        tv[q] = fmaf(gg, s, dd * u);
    }
    ends[ck][ch] = s;
    __syncthreads();

    float p2 = siga * siga, p4 = p2 * p2;
    float a5 = p4 * siga;
    float st = 0.f;
    for (int jj = 0; jj < ck; jj++)
        st = fmaf(a5, st, ends[jj][ch]);
    float gc = gg * st;

    float pw = siga;
#pragma unroll
    for (int q = 0; q < 5; q++) {
        g_u[base + (k0 + q) * INNER_] = fmaf(gc, pw, tv[q]) * bvv[q];
        pw *= siga;
    }
}

// =====================================================================
// Kernel 4: out-projection (bf16-split MMA) + 2h+y residual + rmsnorm.
// =====================================================================
__global__ __launch_bounds__(256) void k_outproj(int woff) {
    __shared__ __align__(16) union {
        struct { bf ah[32][40], al[32][40], wh[128][40], wl[128][40]; } m;
        float hbuf[32][132];
    } s;
    const int t = threadIdx.x, lane = t & 31, w = t >> 5;
    const int mg = w >> 2, nq = w & 3;
    const int growb = blockIdx.x * 32;

    float acc[4][4] = {};

    for (int kch = 0; kch < 8; kch++) {
        {
            int row = t >> 3, f4 = t & 7;
            float4 v = *reinterpret_cast<const float4*>(
                &g_u[(growb + row) * INNER_ + kch * 32 + f4 * 4]);
            bf h[4], l[4];
            split_bf(v.x, h[0], l[0]); split_bf(v.y, h[1], l[1]);
            split_bf(v.z, h[2], l[2]); split_bf(v.w, h[3], l[3]);
            *reinterpret_cast<ull*>(&s.m.ah[row][f4 * 4]) = *reinterpret_cast<ull*>(h);
            *reinterpret_cast<ull*>(&s.m.al[row][f4 * 4]) = *reinterpret_cast<ull*>(l);
        }
#pragma unroll
        for (int q = 0; q < 2; q++) {
            int idx = t + 256 * q;
            int row = idx >> 2, k4 = idx & 3;
            cp16((unsigned)__cvta_generic_to_shared(&s.m.wh[row][k4 * 8]),
                 g_wbh + woff + row * 256 + kch * 32 + k4 * 8);
            cp16((unsigned)__cvta_generic_to_shared(&s.m.wl[row][k4 * 8]),
                 g_wbl + woff + row * 256 + kch * 32 + k4 * 8);
        }
        cp_commit(); cp_waitall();
        __syncthreads();

#pragma unroll
        for (int kst = 0; kst < 2; kst++) {
            const int ko = kst * 16 + 2 * (lane & 3);
            const int r0 = mg * 16 + (lane >> 2);
            unsigned ah[4], al_[4];
            ah[0] = ldu32(&s.m.ah[r0][ko]);     ah[1] = ldu32(&s.m.ah[r0 + 8][ko]);
            ah[2] = ldu32(&s.m.ah[r0][ko + 8]); ah[3] = ldu32(&s.m.ah[r0 + 8][ko + 8]);
            al_[0] = ldu32(&s.m.al[r0][ko]);     al_[1] = ldu32(&s.m.al[r0 + 8][ko]);
            al_[2] = ldu32(&s.m.al[r0][ko + 8]); al_[3] = ldu32(&s.m.al[r0 + 8][ko + 8]);
#pragma unroll
            for (int nt = 0; nt < 4; nt++) {
                int n = nq * 32 + nt * 8 + (lane >> 2);
                unsigned bh0 = ldu32(&s.m.wh[n][ko]), bh1 = ldu32(&s.m.wh[n][ko + 8]);
                unsigned bl0 = ldu32(&s.m.wl[n][ko]), bl1 = ldu32(&s.m.wl[n][ko + 8]);
                mma_bf16(acc[nt], ah, bh0, bh1);
                mma_bf16(acc[nt], ah, bl0, bl1);
                mma_bf16(acc[nt], al_, bh0, bh1);
            }
        }
        __syncthreads();
    }

#pragma unroll
    for (int nt = 0; nt < 4; nt++) {
        int colw = nq * 32 + nt * 8 + 2 * (lane & 3);
        int r0 = mg * 16 + (lane >> 2);
        *reinterpret_cast<float2*>(&s.hbuf[r0][colw]) = make_float2(acc[nt][0], acc[nt][1]);
        *reinterpret_cast<float2*>(&s.hbuf[r0 + 8][colw]) = make_float2(acc[nt][2], acc[nt][3]);
    }
    __syncthreads();

    {
        int row = t >> 3, part = t & 7;
        int grow = growb + row;
        float ssq = 0.f;
#pragma unroll
        for (int j = 0; j < 16; j++) {
            int c = part * 16 + j;
            float nv = 2.f * g_h[grow * 128 + c] + s.hbuf[row][c];
            s.hbuf[row][c] = nv;
            ssq += nv * nv;
        }
        ssq += __shfl_xor_sync(0xffffffffu, ssq, 1);
        ssq += __shfl_xor_sync(0xffffffffu, ssq, 2);
        ssq += __shfl_xor_sync(0xffffffffu, ssq, 4);
        float sc = rsqrtf(ssq * (1.0f / 128.0f) + EPS_);
        if (part == 0) g_scale[grow] = sc;
#pragma unroll
        for (int j = 0; j < 16; j += 2) {
            int c = part * 16 + j;
            float v0 = s.hbuf[row][c], v1 = s.hbuf[row][c + 1];
            *reinterpret_cast<float2*>(&g_h[grow * 128 + c]) = make_float2(v0, v1);
            bf h0, l0, h1, l1;
            split_bf(v0 * sc, h0, l0); split_bf(v1 * sc, h1, l1);
            bf hp[2] = {h0, h1}, lp[2] = {l0, l1};
            *reinterpret_cast<unsigned*>(&g_nhh[grow * 128 + c]) = *reinterpret_cast<unsigned*>(hp);
            *reinterpret_cast<unsigned*>(&g_nhl[grow * 128 + c]) = *reinterpret_cast<unsigned*>(lp);
        }
    }
}

// =====================================================================
// Kernel 5a: normalized flat activations -> bf16 hi/lo split slabs
// =====================================================================
__global__ __launch_bounds__(256) void k_flatcvt(const float* __restrict__ nfw) {
    int idx = blockIdx.x * 256 + threadIdx.x;
    float sc = g_scale[idx >> 5];
    int j4 = idx << 2;
    float4 h = *reinterpret_cast<const float4*>(&g_h[j4]);
    float4 nv = *reinterpret_cast<const float4*>(&nfw[j4 & 127]);
    float vv[4] = {h.x * sc * nv.x, h.y * sc * nv.y, h.z * sc * nv.z, h.w * sc * nv.w};
    bf hv[4], lv[4];
#pragma unroll
    for (int j = 0; j < 4; j++) split_bf(vv[j], hv[j], lv[j]);
    *reinterpret_cast<ull*>(&g_fhi[j4]) = *reinterpret_cast<ull*>(hv);
    *reinterpret_cast<ull*>(&g_flo[j4]) = *reinterpret_cast<ull*>(lv);
}

// =====================================================================
// Kernel 5b: final GEMM (bf16 hi/lo split MMA). Depth-2 register
// prefetch of weights hides most of DRAM latency behind 2 chunks of MMA.
// =====================================================================
__global__ __launch_bounds__(256) void k_final(const float* __restrict__ outW) {
    __shared__ __align__(16) bf fh[32][328];
    __shared__ __align__(16) bf fl[32][328];

    const int t = threadIdx.x;
    const int w = t >> 5, l = t & 31;
    const int g = l >> 2, tig = l & 3;
    const int obase = blockIdx.x * 128;
    const int ks = blockIdx.y;
    const int jbase = ks * 320;

    {
        unsigned fhb = (unsigned)__cvta_generic_to_shared(&fh[0][0]);
        unsigned flb = (unsigned)__cvta_generic_to_shared(&fl[0][0]);
#pragma unroll
        for (int q = 0; q < 5; q++) {
            int c = t + 256 * q;
            int b = c / 40, kc = c - b * 40;
            cp16(fhb + b * 656 + kc * 16, g_fhi + b * DNP_ + jbase + kc * 8);
            cp16(flb + b * 656 + kc * 16, g_flo + b * DNP_ + jbase + kc * 8);
        }
    }
    cp_commit();

    const int n0 = obase + w * 16 + g;
    const float* w0p = outW + (size_t)n0 * DNP_ + jbase + 2 * tig;
    const float* w1p = w0p + (size_t)8 * DNP_;

    float c[2][2][4];
#pragma unroll
    for (int mt = 0; mt < 2; mt++)
#pragma unroll
        for (int nt = 0; nt < 2; nt++)
#pragma unroll
            for (int q = 0; q < 4; q++) c[mt][nt][q] = 0.f;

    // depth-2 prefetch: b0 = chunk ch, b1 = ch+1, load ch+2 into b2
    float2 b0[4], b1[4], b2[4];
#pragma unroll
    for (int q = 0; q < 1; q++) {
        b0[0] = *reinterpret_cast<const float2*>(w0p);
        b0[1] = *reinterpret_cast<const float2*>(w0p + 8);
        b0[2] = *reinterpret_cast<const float2*>(w1p);
        b0[3] = *reinterpret_cast<const float2*>(w1p + 8);
        b1[0] = *reinterpret_cast<const float2*>(w0p + 16);
        b1[1] = *reinterpret_cast<const float2*>(w0p + 24);
        b1[2] = *reinterpret_cast<const float2*>(w1p + 16);
        b1[3] = *reinterpret_cast<const float2*>(w1p + 24);
    }

    cp_waitall();
    __syncthreads();

    for (int ch = 0; ch < 20; ch++) {
        // issue load for ch+2 first (deep prefetch)
        int chn = (ch + 2 < 20) ? (ch + 2) : 19;
        b2[0] = *reinterpret_cast<const float2*>(w0p + chn * 16);
        b2[1] = *reinterpret_cast<const float2*>(w0p + chn * 16 + 8);
        b2[2] = *reinterpret_cast<const float2*>(w1p + chn * 16);
        b2[3] = *reinterpret_cast<const float2*>(w1p + chn * 16 + 8);

        const int off = ch * 16 + 2 * tig;
        unsigned ahi[2][4], alo[2][4];
#pragma unroll
        for (int mt = 0; mt < 2; mt++) {
            int r = g + mt * 16;
            ahi[mt][0] = ldu32(&fh[r][off]);
            ahi[mt][1] = ldu32(&fh[r + 8][off]);
            ahi[mt][2] = ldu32(&fh[r][off + 8]);
            ahi[mt][3] = ldu32(&fh[r + 8][off + 8]);
            alo[mt][0] = ldu32(&fl[r][off]);
            alo[mt][1] = ldu32(&fl[r + 8][off]);
            alo[mt][2] = ldu32(&fl[r][off + 8]);
            alo[mt][3] = ldu32(&fl[r + 8][off + 8]);
        }

        unsigned bhi[2][2], blo[2][2];
#pragma unroll
        for (int nt = 0; nt < 2; nt++) {
#pragma unroll
            for (int hb = 0; hb < 2; hb++) {
                float2 wv = b0[nt * 2 + hb];
                __nv_bfloat162 h2 = __floats2bfloat162_rn(wv.x, wv.y);
                float2 lo2 = make_float2(wv.x - __bfloat162float(__low2bfloat16(h2)),
                                         wv.y - __bfloat162float(__high2bfloat16(h2)));
                __nv_bfloat162 l2 = __floats2bfloat162_rn(lo2.x, lo2.y);
                bhi[nt][hb] = *reinterpret_cast<unsigned*>(&h2);
                blo[nt][hb] = *reinterpret_cast<unsigned*>(&l2);
            }
        }

#pragma unroll
        for (int mt = 0; mt < 2; mt++)
#pragma unroll
            for (int nt = 0; nt < 2; nt++) {
                mma_bf16(c[mt][nt], ahi[mt], bhi[nt][0], bhi[nt][1]);
                mma_bf16(c[mt][nt], ahi[mt], blo[nt][0], blo[nt][1]);
                mma_bf16(c[mt][nt], alo[mt], bhi[nt][0], bhi[nt][1]);
            }

#pragma unroll
        for (int q = 0; q < 4; q++) { b0[q] = b1[q]; b1[q] = b2[q]; }
    }

#pragma unroll
    for (int mt = 0; mt < 2; mt++)
#pragma unroll
        for (int nt = 0; nt < 2; nt++) {
            int o = obase + w * 16 + nt * 8 + 2 * tig;
            int b0i = g + mt * 16;
            float* p0 = &g_part[(ks * B_ + b0i) * CF_ + o];
            float* p1 = &g_part[(ks * B_ + b0i + 8) * CF_ + o];
            *reinterpret_cast<float2*>(p0) = make_float2(c[mt][nt][0], c[mt][nt][1]);
            *reinterpret_cast<float2*>(p1) = make_float2(c[mt][nt][2], c[mt][nt][3]);
        }
}

// Kernel 6: reduce split-K partials + bias -> d_out (deterministic)
__global__ __launch_bounds__(256) void k_reduce(const float* __restrict__ outb,
                                                float* __restrict__ out) {
    int idx = blockIdx.x * 256 + threadIdx.x;
    int b = idx / CF_, o = idx - b * CF_;
    float v = outb[o];
#pragma unroll
    for (int s = 0; s < KS_; s++) v += g_part[(s * B_ + b) * CF_ + o];
    out[idx] = v;
}

// =====================================================================
extern "C" void kernel_launch(void* const* d_in, const int* in_sizes, int n_in,
                              void* d_out, int out_size) {
    const float* x     = (const float*)d_in[0];
    const float* peW   = (const float*)d_in[1];
    const float* peb   = (const float*)d_in[2];
    const float* normw = (const float*)d_in[3];
    const float* ipaW  = (const float*)d_in[4];
    const float* ipbW  = (const float*)d_in[5];
    const float* convW = (const float*)d_in[6];
    const float* convb = (const float*)d_in[7];
    const float* alp   = (const float*)d_in[8];
    const float* bet   = (const float*)d_in[9];
    const float* gam   = (const float*)d_in[10];
    const float* del   = (const float*)d_in[11];
    const float* opW   = (const float*)d_in[12];
    const float* normf = (const float*)d_in[13];
    const float* outW  = (const float*)d_in[14];
    const float* outb  = (const float*)d_in[15];
    float* out = (float*)d_out;

    k_prep_all<<<(PREP_TOT + 255) / 256, 256>>>(peW, normw, ipaW, ipbW, opW);
    k_embed<<<M_ / 32, 256>>>(x, peb);
    for (int l = 0; l < 4; l++) {
        int lb = WSZ_EMB + l * WSZ_LAYER;
        k_inproj<<<dim3(M_ / 32, 4), 256>>>(lb);
        k_convscan<<<B_ * 8, 800>>>(convW + l * INNER_ * 5, convb + l * INNER_,
                                    alp + l * INNER_, bet + l * INNER_,
                                    gam + l * INNER_, del + l * INNER_);
        k_outproj<<<M_ / 32, 256>>>(lb + 65536);
    }
    k_flatcvt<<<500, 256>>>(normf);
    k_final<<<dim3(CF_ / 128, KS_), 256>>>(outW);
    k_reduce<<<(B_ * CF_) / 256, 256>>>(outb, out);
}

// round 10
// speedup vs baseline: 3.6652x; 1.1721x over previous
#include <cuda_runtime.h>
#include <cuda_bf16.h>
#include <math.h>

using ull = unsigned long long;
using bf = __nv_bfloat16;

constexpr int B_   = 32;
constexpr int C_   = 64;
constexpr int L_   = 512;
constexpr int NP_  = 125;
constexpr int D_   = 128;
constexpr int INNER_ = 256;
constexpr int M_   = B_ * NP_;    // 4000
constexpr int CF_  = 6144;        // C*F
constexpr int DNP_ = 16000;       // D*NP
constexpr int KS_  = 50;          // split-K for final GEMM (320 k each)
constexpr float EPS_ = 1e-5f;

// weight slab offsets (bf16 hi/lo converted once per launch)
constexpr int WOFF_EMB = 0;                 // 128 x 1024
constexpr int WSZ_EMB  = 128 * 1024;
constexpr int WSZ_LAYER = 2 * 256 * 128 + 128 * 256;  // ipa+ipb + op = 98304
constexpr int WTOT = WSZ_EMB + 4 * WSZ_LAYER;         // 524288
constexpr int PREP_TOT = WTOT + NP_ * D_;             // + PE table

// dynamic smem sizes
constexpr int SM_EMB = 25600 * 2;     // 50 KB  (double-buffered chunks)
constexpr int SM_IP  = 43520 * 2;     // 85 KB  (full K=128 resident)
constexpr int SM_OP  = 84480 * 2;     // 165 KB (full K=256 resident)

// -------- device scratch (no allocation allowed) --------
__device__ float g_h[M_ * D_];          // hidden (fp32, residual base)
__device__ float g_scale[M_];           // rmsnorm scale per row (final norm)
__device__ float g_a[M_ * INNER_];      // in-proj a
__device__ float g_bv[M_ * INNER_];     // in-proj b
__device__ float g_u[M_ * INNER_];      // gated scan out
__device__ float g_part[KS_ * B_ * CF_];// split-K partials
__device__ float g_pe[NP_ * D_];        // accurate sincos PE table
__device__ bf g_fhi[B_ * DNP_];         // normalized flat, bf16 hi
__device__ bf g_flo[B_ * DNP_];         // normalized flat, bf16 lo
__device__ bf g_nhh[M_ * D_];           // normalized hidden, bf16 hi
__device__ bf g_nhl[M_ * D_];           // normalized hidden, bf16 lo
__device__ bf g_wbh[WTOT];              // weights bf16 hi
__device__ bf g_wbl[WTOT];              // weights bf16 lo

__device__ __forceinline__ void cp16(unsigned s, const void* g) {
    asm volatile("cp.async.cg.shared.global [%0],[%1],16;" :: "r"(s), "l"(g));
}
__device__ __forceinline__ void cp_commit() { asm volatile("cp.async.commit_group;"); }
__device__ __forceinline__ void cp_waitall() { asm volatile("cp.async.wait_group 0;" ::: "memory"); }

__device__ __forceinline__ void mma_bf16(float* c, const unsigned* a,
                                         unsigned b0, unsigned b1) {
    asm volatile(
        "mma.sync.aligned.m16n8k16.row.col.f32.bf16.bf16.f32 "
        "{%0,%1,%2,%3}, {%4,%5,%6,%7}, {%8,%9}, {%0,%1,%2,%3};"
        : "+f"(c[0]), "+f"(c[1]), "+f"(c[2]), "+f"(c[3])
        : "r"(a[0]), "r"(a[1]), "r"(a[2]), "r"(a[3]), "r"(b0), "r"(b1));
}
__device__ __forceinline__ unsigned ldu32(const bf* p) {
    return *reinterpret_cast<const unsigned*>(p);
}
__device__ __forceinline__ void split_bf(float v, bf& h, bf& l) {
    h = __float2bfloat16(v);
    l = __float2bfloat16(v - __bfloat162float(h));
}

// =====================================================================
// Kernel 0: merged prep — weight slabs (bf16 hi/lo) + PE table.
// =====================================================================
__global__ __launch_bounds__(256) void k_prep_all(const float* __restrict__ peW,
                                                  const float* __restrict__ normw,
                                                  const float* __restrict__ ipaW,
                                                  const float* __restrict__ ipbW,
                                                  const float* __restrict__ opW) {
    int idx = blockIdx.x * 256 + threadIdx.x;
    if (idx >= PREP_TOT) return;
    if (idx >= WTOT) {
        int p = idx - WTOT;
        int kq = p >> 7, col = p & 127;
        int ii = col >> 1;
        float targ = (-9.210340371976184f) * (float)ii * (1.0f / 64.0f);
        float divf = (float)exp((double)targ);
        float ang = (float)kq * divf;
        double a = (double)ang;
        g_pe[p] = (float)((col & 1) ? cos(a) : sin(a));
        return;
    }
    float v;
    if (idx < WSZ_EMB) {
        v = peW[idx];
    } else {
        int r = idx - WSZ_EMB;
        int l = r / WSZ_LAYER;
        int o = r - l * WSZ_LAYER;
        if (o < 32768)       v = ipaW[l * 32768 + o] * normw[l * 128 + (o & 127)];
        else if (o < 65536)  v = ipbW[l * 32768 + (o - 32768)] * normw[l * 128 + (o & 127)];
        else                 v = opW[l * 32768 + (o - 65536)];
    }
    bf h, l2; split_bf(v, h, l2);
    g_wbh[idx] = h;
    g_wbl[idx] = l2;
}

// =====================================================================
// Kernel 1: patch-embed GEMM, DOUBLE-BUFFERED chunks (dyn smem 50KB).
// layout (bf units): ah[b]=b*1280; al[b]=2560+b*1280;
//                    wh[b]=5120+b*5120; wl[b]=15360+b*5120
// =====================================================================
__global__ __launch_bounds__(256) void k_embed(const float* __restrict__ x,
                                               const float* __restrict__ peb) {
    extern __shared__ __align__(16) bf sm[];
    const int t = threadIdx.x, lane = t & 31, w = t >> 5;
    const int mg = w >> 2, nq = w & 3;
    const int growb = blockIdx.x * 32;

    auto stage = [&](int kch, int buf) {
        bf* ah = sm + buf * 1280;
        bf* al = sm + 2560 + buf * 1280;
#pragma unroll
        for (int q = 0; q < 4; q++) {
            int idx = t + 256 * q;
            int row = idx >> 5, kk = idx & 31;
            int gk = kch * 32 + kk, c = gk >> 4, p = gk & 15;
            int grow = growb + row, bb = grow / 125, kq = grow - bb * 125;
            float v = x[(bb * C_ + c) * L_ + kq * 4 + p];
            split_bf(v, ah[row * 40 + kk], al[row * 40 + kk]);
        }
        unsigned whb = (unsigned)__cvta_generic_to_shared(sm + 5120 + buf * 5120);
        unsigned wlb = (unsigned)__cvta_generic_to_shared(sm + 15360 + buf * 5120);
#pragma unroll
        for (int q = 0; q < 2; q++) {
            int idx = t + 256 * q;
            int row = idx >> 2, k4 = idx & 3;
            cp16(whb + row * 80 + k4 * 16, g_wbh + WOFF_EMB + row * 1024 + kch * 32 + k4 * 8);
            cp16(wlb + row * 80 + k4 * 16, g_wbl + WOFF_EMB + row * 1024 + kch * 32 + k4 * 8);
        }
        cp_commit();
    };

    float acc[4][4] = {};
    stage(0, 0);

    for (int kch = 0; kch < 32; kch++) {
        const int buf = kch & 1;
        cp_waitall();
        __syncthreads();
        if (kch + 1 < 32) stage(kch + 1, buf ^ 1);

        const bf* ah = sm + buf * 1280;
        const bf* al = sm + 2560 + buf * 1280;
        const bf* wh = sm + 5120 + buf * 5120;
        const bf* wl = sm + 15360 + buf * 5120;
#pragma unroll
        for (int kst = 0; kst < 2; kst++) {
            const int ko = kst * 16 + 2 * (lane & 3);
            const int r0 = mg * 16 + (lane >> 2);
            unsigned af[4], alf[4];
            af[0] = ldu32(&ah[r0 * 40 + ko]);       af[1] = ldu32(&ah[(r0 + 8) * 40 + ko]);
            af[2] = ldu32(&ah[r0 * 40 + ko + 8]);   af[3] = ldu32(&ah[(r0 + 8) * 40 + ko + 8]);
            alf[0] = ldu32(&al[r0 * 40 + ko]);      alf[1] = ldu32(&al[(r0 + 8) * 40 + ko]);
            alf[2] = ldu32(&al[r0 * 40 + ko + 8]);  alf[3] = ldu32(&al[(r0 + 8) * 40 + ko + 8]);
#pragma unroll
            for (int nt = 0; nt < 4; nt++) {
                int n = nq * 32 + nt * 8 + (lane >> 2);
                unsigned bh0 = ldu32(&wh[n * 40 + ko]), bh1 = ldu32(&wh[n * 40 + ko + 8]);
                unsigned bl0 = ldu32(&wl[n * 40 + ko]), bl1 = ldu32(&wl[n * 40 + ko + 8]);
                mma_bf16(acc[nt], af, bh0, bh1);
                mma_bf16(acc[nt], af, bl0, bl1);
                mma_bf16(acc[nt], alf, bh0, bh1);
            }
        }
        __syncthreads();
    }

    // epilogue via hbuf overlay
    float (*hbuf)[132] = reinterpret_cast<float(*)[132]>(sm);
#pragma unroll
    for (int nt = 0; nt < 4; nt++) {
        int colw = nq * 32 + nt * 8 + 2 * (lane & 3);
        int r0 = mg * 16 + (lane >> 2);
        *reinterpret_cast<float2*>(&hbuf[r0][colw]) = make_float2(acc[nt][0], acc[nt][1]);
        *reinterpret_cast<float2*>(&hbuf[r0 + 8][colw]) = make_float2(acc[nt][2], acc[nt][3]);
    }
    __syncthreads();

    {
        int row = t >> 3, part = t & 7;
        int grow = growb + row, bb = grow / 125, kq = grow - bb * 125;
        float ssq = 0.f;
#pragma unroll
        for (int j = 0; j < 16; j++) {
            int c = part * 16 + j;
            float v = hbuf[row][c] + peb[c] + g_pe[kq * 128 + c];
            hbuf[row][c] = v;
            ssq += v * v;
        }
        ssq += __shfl_xor_sync(0xffffffffu, ssq, 1);
        ssq += __shfl_xor_sync(0xffffffffu, ssq, 2);
        ssq += __shfl_xor_sync(0xffffffffu, ssq, 4);
        float sc = rsqrtf(ssq * (1.0f / 128.0f) + EPS_);
        if (part == 0) g_scale[grow] = sc;
#pragma unroll
        for (int j = 0; j < 16; j += 2) {
            int c = part * 16 + j;
            float v0 = hbuf[row][c], v1 = hbuf[row][c + 1];
            *reinterpret_cast<float2*>(&g_h[grow * 128 + c]) = make_float2(v0, v1);
            bf h0, l0, h1, l1;
            split_bf(v0 * sc, h0, l0); split_bf(v1 * sc, h1, l1);
            bf hp[2] = {h0, h1}, lp[2] = {l0, l1};
            *reinterpret_cast<unsigned*>(&g_nhh[grow * 128 + c]) = *reinterpret_cast<unsigned*>(hp);
            *reinterpret_cast<unsigned*>(&g_nhl[grow * 128 + c]) = *reinterpret_cast<unsigned*>(lp);
        }
    }
}

// =====================================================================
// Kernel 2: in-projections — FULL K=128 resident (dyn smem 85KB).
// layout (bf units, row stride 136): ah=0; al=4352; wh=8704; wl=26112
// One cp.async wave, one sync, 8 MMA steps with no barriers.
// =====================================================================
__global__ __launch_bounds__(256) void k_inproj(int lbase) {
    extern __shared__ __align__(16) bf sm[];
    bf* ah = sm;            bf* al = sm + 4352;
    bf* wh = sm + 8704;     bf* wl = sm + 26112;
    const int t = threadIdx.x, lane = t & 31, w = t >> 5;
    const int mg = w >> 2, nq = w & 3;
    const int growb = blockIdx.x * 32;
    const int ny = blockIdx.y;
    const int woff = lbase + ny * 128 * 128;

    {
        unsigned ahb = (unsigned)__cvta_generic_to_shared(ah);
        unsigned alb = (unsigned)__cvta_generic_to_shared(al);
        unsigned whb = (unsigned)__cvta_generic_to_shared(wh);
        unsigned wlb = (unsigned)__cvta_generic_to_shared(wl);
        // A: 32 rows x 16 chunks per slab
#pragma unroll
        for (int q = 0; q < 2; q++) {
            int idx = t + 256 * q;
            int row = idx >> 4, k4 = idx & 15;
            cp16(ahb + row * 272 + k4 * 16, g_nhh + (growb + row) * 128 + k4 * 8);
            cp16(alb + row * 272 + k4 * 16, g_nhl + (growb + row) * 128 + k4 * 8);
        }
        // W: 128 rows x 16 chunks per slab
#pragma unroll
        for (int q = 0; q < 8; q++) {
            int idx = t + 256 * q;
            int row = idx >> 4, k4 = idx & 15;
            cp16(whb + row * 272 + k4 * 16, g_wbh + woff + row * 128 + k4 * 8);
            cp16(wlb + row * 272 + k4 * 16, g_wbl + woff + row * 128 + k4 * 8);
        }
        cp_commit(); cp_waitall();
        __syncthreads();
    }

    float acc[4][4] = {};
#pragma unroll
    for (int kst = 0; kst < 8; kst++) {
        const int ko = kst * 16 + 2 * (lane & 3);
        const int r0 = mg * 16 + (lane >> 2);
        unsigned af[4], alf[4];
        af[0] = ldu32(&ah[r0 * 136 + ko]);       af[1] = ldu32(&ah[(r0 + 8) * 136 + ko]);
        af[2] = ldu32(&ah[r0 * 136 + ko + 8]);   af[3] = ldu32(&ah[(r0 + 8) * 136 + ko + 8]);
        alf[0] = ldu32(&al[r0 * 136 + ko]);      alf[1] = ldu32(&al[(r0 + 8) * 136 + ko]);
        alf[2] = ldu32(&al[r0 * 136 + ko + 8]);  alf[3] = ldu32(&al[(r0 + 8) * 136 + ko + 8]);
#pragma unroll
        for (int nt = 0; nt < 4; nt++) {
            int n = nq * 32 + nt * 8 + (lane >> 2);
            unsigned bh0 = ldu32(&wh[n * 136 + ko]), bh1 = ldu32(&wh[n * 136 + ko + 8]);
            unsigned bl0 = ldu32(&wl[n * 136 + ko]), bl1 = ldu32(&wl[n * 136 + ko + 8]);
            mma_bf16(acc[nt], af, bh0, bh1);
            mma_bf16(acc[nt], af, bl0, bl1);
            mma_bf16(acc[nt], alf, bh0, bh1);
        }
    }

    float* out = (ny < 2) ? g_a : g_bv;
    const int colb = (ny & 1) * 128;
#pragma unroll
    for (int nt = 0; nt < 4; nt++) {
        int col = colb + nq * 32 + nt * 8 + 2 * (lane & 3);
        int r0 = growb + mg * 16 + (lane >> 2);
        *reinterpret_cast<float2*>(&out[r0 * INNER_ + col]) = make_float2(acc[nt][0], acc[nt][1]);
        *reinterpret_cast<float2*>(&out[(r0 + 8) * INNER_ + col]) = make_float2(acc[nt][2], acc[nt][3]);
    }
}

// =====================================================================
// Kernel 3: conv + silu + chunked parallel scan + b-gate (unchanged).
// =====================================================================
__global__ __launch_bounds__(800) void k_convscan(const float* __restrict__ cw,
                                                  const float* __restrict__ cb,
                                                  const float* __restrict__ al,
                                                  const float* __restrict__ be,
                                                  const float* __restrict__ ga,
                                                  const float* __restrict__ de) {
    __shared__ float ends[25][32];
    const int t = threadIdx.x;
    const int ch = t & 31, ck = t >> 5;
    const int b = blockIdx.x >> 3;
    const int ig = blockIdx.x & 7;
    const int i = ig * 32 + ch;
    const int base = b * 125 * INNER_ + i;
    const int k0 = ck * 5;

    const float* w = cw + i * 5;
    const float w0 = w[0], w1 = w[1], w2 = w[2], w3 = w[3], w4 = w[4];
    const float bias = cb[i];
    const float siga = 1.f / (1.f + __expf(-al[i]));
    const float bb = be[i], gg = ga[i], dd = de[i];

    float av[9];
#pragma unroll
    for (int q = 0; q < 9; q++) {
        int kk = k0 - 2 + q;
        av[q] = (kk >= 0 && kk <= 124) ? g_a[base + kk * INNER_] : 0.f;
    }
    float bvv[5];
#pragma unroll
    for (int q = 0; q < 5; q++) bvv[q] = g_bv[base + (k0 + q) * INNER_];

    float tv[5];
    float s = 0.f;
#pragma unroll
    for (int q = 0; q < 5; q++) {
        float acc = bias;
        acc = fmaf(w0, av[q], acc);
        acc = fmaf(w1, av[q + 1], acc);
        acc = fmaf(w2, av[q + 2], acc);
        acc = fmaf(w3, av[q + 3], acc);
        acc = fmaf(w4, av[q + 4], acc);
        float u = acc / (1.f + __expf(-acc));
        s = fmaf(siga, s, bb * u);
        tv[q] = fmaf(gg, s, dd * u);
    }
    ends[ck][ch] = s;
    __syncthreads();

    float p2 = siga * siga, p4 = p2 * p2;
    float a5 = p4 * siga;
    float st = 0.f;
    for (int jj = 0; jj < ck; jj++)
        st = fmaf(a5, st, ends[jj][ch]);
    float gc = gg * st;

    float pw = siga;
#pragma unroll
    for (int q = 0; q < 5; q++) {
        g_u[base + (k0 + q) * INNER_] = fmaf(gc, pw, tv[q]) * bvv[q];
        pw *= siga;
    }
}

// =====================================================================
// Kernel 4: out-projection — FULL K=256 resident (dyn smem 165KB).
// layout (bf units, row stride 264): ah=0; al=8448; wh=16896; wl=50688
// =====================================================================
__global__ __launch_bounds__(256) void k_outproj(int woff) {
    extern __shared__ __align__(16) bf sm[];
    bf* ah = sm;             bf* al = sm + 8448;
    bf* wh = sm + 16896;     bf* wl = sm + 50688;
    const int t = threadIdx.x, lane = t & 31, w = t >> 5;
    const int mg = w >> 2, nq = w & 3;
    const int growb = blockIdx.x * 32;

    {
        unsigned whb = (unsigned)__cvta_generic_to_shared(wh);
        unsigned wlb = (unsigned)__cvta_generic_to_shared(wl);
#pragma unroll
        for (int q = 0; q < 16; q++) {
            int idx = t + 256 * q;
            int row = idx >> 5, k4 = idx & 31;
            cp16(whb + row * 528 + k4 * 16, g_wbh + woff + row * 256 + k4 * 8);
            cp16(wlb + row * 528 + k4 * 16, g_wbl + woff + row * 256 + k4 * 8);
        }
        cp_commit();
        // A: fp32 g_u -> split (direct stores, overlap with W cp.async)
#pragma unroll
        for (int q = 0; q < 8; q++) {
            int idx = t + 256 * q;
            int row = idx >> 6, f4 = idx & 63;
            float4 v = *reinterpret_cast<const float4*>(&g_u[(growb + row) * INNER_ + f4 * 4]);
            bf h[4], l[4];
            split_bf(v.x, h[0], l[0]); split_bf(v.y, h[1], l[1]);
            split_bf(v.z, h[2], l[2]); split_bf(v.w, h[3], l[3]);
            *reinterpret_cast<ull*>(&ah[row * 264 + f4 * 4]) = *reinterpret_cast<ull*>(h);
            *reinterpret_cast<ull*>(&al[row * 264 + f4 * 4]) = *reinterpret_cast<ull*>(l);
        }
        cp_waitall();
        __syncthreads();
    }

    float acc[4][4] = {};
#pragma unroll
    for (int kst = 0; kst < 16; kst++) {
        const int ko = kst * 16 + 2 * (lane & 3);
        const int r0 = mg * 16 + (lane >> 2);
        unsigned af[4], alf[4];
        af[0] = ldu32(&ah[r0 * 264 + ko]);       af[1] = ldu32(&ah[(r0 + 8) * 264 + ko]);
        af[2] = ldu32(&ah[r0 * 264 + ko + 8]);   af[3] = ldu32(&ah[(r0 + 8) * 264 + ko + 8]);
        alf[0] = ldu32(&al[r0 * 264 + ko]);      alf[1] = ldu32(&al[(r0 + 8) * 264 + ko]);
        alf[2] = ldu32(&al[r0 * 264 + ko + 8]);  alf[3] = ldu32(&al[(r0 + 8) * 264 + ko + 8]);
#pragma unroll
        for (int nt = 0; nt < 4; nt++) {
            int n = nq * 32 + nt * 8 + (lane >> 2);
            unsigned bh0 = ldu32(&wh[n * 264 + ko]), bh1 = ldu32(&wh[n * 264 + ko + 8]);
            unsigned bl0 = ldu32(&wl[n * 264 + ko]), bl1 = ldu32(&wl[n * 264 + ko + 8]);
            mma_bf16(acc[nt], af, bh0, bh1);
            mma_bf16(acc[nt], af, bl0, bl1);
            mma_bf16(acc[nt], alf, bh0, bh1);
        }
    }
    __syncthreads();

    // epilogue via hbuf overlay (A region no longer needed)
    float (*hbuf)[132] = reinterpret_cast<float(*)[132]>(sm);
#pragma unroll
    for (int nt = 0; nt < 4; nt++) {
        int colw = nq * 32 + nt * 8 + 2 * (lane & 3);
        int r0 = mg * 16 + (lane >> 2);
        *reinterpret_cast<float2*>(&hbuf[r0][colw]) = make_float2(acc[nt][0], acc[nt][1]);
        *reinterpret_cast<float2*>(&hbuf[r0 + 8][colw]) = make_float2(acc[nt][2], acc[nt][3]);
    }
    __syncthreads();

    {
        int row = t >> 3, part = t & 7;
        int grow = growb + row;
        float ssq = 0.f;
#pragma unroll
        for (int j = 0; j < 16; j++) {
            int c = part * 16 + j;
            float nv = 2.f * g_h[grow * 128 + c] + hbuf[row][c];
            hbuf[row][c] = nv;
            ssq += nv * nv;
        }
        ssq += __shfl_xor_sync(0xffffffffu, ssq, 1);
        ssq += __shfl_xor_sync(0xffffffffu, ssq, 2);
        ssq += __shfl_xor_sync(0xffffffffu, ssq, 4);
        float sc = rsqrtf(ssq * (1.0f / 128.0f) + EPS_);
        if (part == 0) g_scale[grow] = sc;
#pragma unroll
        for (int j = 0; j < 16; j += 2) {
            int c = part * 16 + j;
            float v0 = hbuf[row][c], v1 = hbuf[row][c + 1];
            *reinterpret_cast<float2*>(&g_h[grow * 128 + c]) = make_float2(v0, v1);
            bf h0, l0, h1, l1;
            split_bf(v0 * sc, h0, l0); split_bf(v1 * sc, h1, l1);
            bf hp[2] = {h0, h1}, lp[2] = {l0, l1};
            *reinterpret_cast<unsigned*>(&g_nhh[grow * 128 + c]) = *reinterpret_cast<unsigned*>(hp);
            *reinterpret_cast<unsigned*>(&g_nhl[grow * 128 + c]) = *reinterpret_cast<unsigned*>(lp);
        }
    }
}

// =====================================================================
// Kernel 5a: normalized flat activations -> bf16 hi/lo split slabs
// =====================================================================
__global__ __launch_bounds__(256) void k_flatcvt(const float* __restrict__ nfw) {
    int idx = blockIdx.x * 256 + threadIdx.x;
    float sc = g_scale[idx >> 5];
    int j4 = idx << 2;
    float4 h = *reinterpret_cast<const float4*>(&g_h[j4]);
    float4 nv = *reinterpret_cast<const float4*>(&nfw[j4 & 127]);
    float vv[4] = {h.x * sc * nv.x, h.y * sc * nv.y, h.z * sc * nv.z, h.w * sc * nv.w};
    bf hv[4], lv[4];
#pragma unroll
    for (int j = 0; j < 4; j++) split_bf(vv[j], hv[j], lv[j]);
    *reinterpret_cast<ull*>(&g_fhi[j4]) = *reinterpret_cast<ull*>(hv);
    *reinterpret_cast<ull*>(&g_flo[j4]) = *reinterpret_cast<ull*>(lv);
}

// =====================================================================
// Kernel 5b: final GEMM (bf16 hi/lo split MMA). REVERTED to depth-1
// weight prefetch (depth-2 regressed via register pressure).
// =====================================================================
__global__ __launch_bounds__(256) void k_final(const float* __restrict__ outW) {
    __shared__ __align__(16) bf fh[32][328];
    __shared__ __align__(16) bf fl[32][328];

    const int t = threadIdx.x;
    const int w = t >> 5, l = t & 31;
    const int g = l >> 2, tig = l & 3;
    const int obase = blockIdx.x * 128;
    const int ks = blockIdx.y;
    const int jbase = ks * 320;

    {
        unsigned fhb = (unsigned)__cvta_generic_to_shared(&fh[0][0]);
        unsigned flb = (unsigned)__cvta_generic_to_shared(&fl[0][0]);
#pragma unroll
        for (int q = 0; q < 5; q++) {
            int c = t + 256 * q;
            int b = c / 40, kc = c - b * 40;
            cp16(fhb + b * 656 + kc * 16, g_fhi + b * DNP_ + jbase + kc * 8);
            cp16(flb + b * 656 + kc * 16, g_flo + b * DNP_ + jbase + kc * 8);
        }
    }
    cp_commit();

    const int n0 = obase + w * 16 + g;
    const float* w0p = outW + (size_t)n0 * DNP_ + jbase + 2 * tig;
    const float* w1p = w0p + (size_t)8 * DNP_;

    float c[2][2][4];
#pragma unroll
    for (int mt = 0; mt < 2; mt++)
#pragma unroll
        for (int nt = 0; nt < 2; nt++)
#pragma unroll
            for (int q = 0; q < 4; q++) c[mt][nt][q] = 0.f;

    float2 cur[4] = { *reinterpret_cast<const float2*>(w0p),
                      *reinterpret_cast<const float2*>(w0p + 8),
                      *reinterpret_cast<const float2*>(w1p),
                      *reinterpret_cast<const float2*>(w1p + 8) };

    cp_waitall();
    __syncthreads();

    for (int ch = 0; ch < 20; ch++) {
        int chn = (ch + 1 < 20) ? (ch + 1) : 19;
        float2 nxt[4] = { *reinterpret_cast<const float2*>(w0p + chn * 16),
                          *reinterpret_cast<const float2*>(w0p + chn * 16 + 8),
                          *reinterpret_cast<const float2*>(w1p + chn * 16),
                          *reinterpret_cast<const float2*>(w1p + chn * 16 + 8) };

        const int off = ch * 16 + 2 * tig;
        unsigned ahi[2][4], alo[2][4];
#pragma unroll
        for (int mt = 0; mt < 2; mt++) {
            int r = g + mt * 16;
            ahi[mt][0] = ldu32(&fh[r][off]);
            ahi[mt][1] = ldu32(&fh[r + 8][off]);
            ahi[mt][2] = ldu32(&fh[r][off + 8]);
            ahi[mt][3] = ldu32(&fh[r + 8][off + 8]);
            alo[mt][0] = ldu32(&fl[r][off]);
            alo[mt][1] = ldu32(&fl[r + 8][off]);
            alo[mt][2] = ldu32(&fl[r][off + 8]);
            alo[mt][3] = ldu32(&fl[r + 8][off + 8]);
        }

        unsigned bhi[2][2], blo[2][2];
#pragma unroll
        for (int nt = 0; nt < 2; nt++) {
#pragma unroll
            for (int hb = 0; hb < 2; hb++) {
                float2 wv = cur[nt * 2 + hb];
                __nv_bfloat162 h2 = __floats2bfloat162_rn(wv.x, wv.y);
                float2 lo2 = make_float2(wv.x - __bfloat162float(__low2bfloat16(h2)),
                                         wv.y - __bfloat162float(__high2bfloat16(h2)));
                __nv_bfloat162 l2 = __floats2bfloat162_rn(lo2.x, lo2.y);
                bhi[nt][hb] = *reinterpret_cast<unsigned*>(&h2);
                blo[nt][hb] = *reinterpret_cast<unsigned*>(&l2);
            }
        }

#pragma unroll
        for (int mt = 0; mt < 2; mt++)
#pragma unroll
            for (int nt = 0; nt < 2; nt++) {
                mma_bf16(c[mt][nt], ahi[mt], bhi[nt][0], bhi[nt][1]);
                mma_bf16(c[mt][nt], ahi[mt], blo[nt][0], blo[nt][1]);
                mma_bf16(c[mt][nt], alo[mt], bhi[nt][0], bhi[nt][1]);
            }

#pragma unroll
        for (int q = 0; q < 4; q++) cur[q] = nxt[q];
    }

#pragma unroll
    for (int mt = 0; mt < 2; mt++)
#pragma unroll
        for (int nt = 0; nt < 2; nt++) {
            int o = obase + w * 16 + nt * 8 + 2 * tig;
            int b0i = g + mt * 16;
            float* p0 = &g_part[(ks * B_ + b0i) * CF_ + o];
            float* p1 = &g_part[(ks * B_ + b0i + 8) * CF_ + o];
            *reinterpret_cast<float2*>(p0) = make_float2(c[mt][nt][0], c[mt][nt][1]);
            *reinterpret_cast<float2*>(p1) = make_float2(c[mt][nt][2], c[mt][nt][3]);
        }
}

// Kernel 6: reduce split-K partials + bias -> d_out (deterministic)
__global__ __launch_bounds__(256) void k_reduce(const float* __restrict__ outb,
                                                float* __restrict__ out) {
    int idx = blockIdx.x * 256 + threadIdx.x;
    int b = idx / CF_, o = idx - b * CF_;
    float v = outb[o];
#pragma unroll
    for (int s = 0; s < KS_; s++) v += g_part[(s * B_ + b) * CF_ + o];
    out[idx] = v;
}

// =====================================================================
extern "C" void kernel_launch(void* const* d_in, const int* in_sizes, int n_in,
                              void* d_out, int out_size) {
    const float* x     = (const float*)d_in[0];
    const float* peW   = (const float*)d_in[1];
    const float* peb   = (const float*)d_in[2];
    const float* normw = (const float*)d_in[3];
    const float* ipaW  = (const float*)d_in[4];
    const float* ipbW  = (const float*)d_in[5];
    const float* convW = (const float*)d_in[6];
    const float* convb = (const float*)d_in[7];
    const float* alp   = (const float*)d_in[8];
    const float* bet   = (const float*)d_in[9];
    const float* gam   = (const float*)d_in[10];
    const float* del   = (const float*)d_in[11];
    const float* opW   = (const float*)d_in[12];
    const float* normf = (const float*)d_in[13];
    const float* outW  = (const float*)d_in[14];
    const float* outb  = (const float*)d_in[15];
    float* out = (float*)d_out;

    // raise dynamic smem limits (idempotent, not an allocation)
    cudaFuncSetAttribute(k_embed,   cudaFuncAttributeMaxDynamicSharedMemorySize, SM_EMB);
    cudaFuncSetAttribute(k_inproj,  cudaFuncAttributeMaxDynamicSharedMemorySize, SM_IP);
    cudaFuncSetAttribute(k_outproj, cudaFuncAttributeMaxDynamicSharedMemorySize, SM_OP);

    k_prep_all<<<(PREP_TOT + 255) / 256, 256>>>(peW, normw, ipaW, ipbW, opW);
    k_embed<<<M_ / 32, 256, SM_EMB>>>(x, peb);
    for (int l = 0; l < 4; l++) {
        int lb = WSZ_EMB + l * WSZ_LAYER;
        k_inproj<<<dim3(M_ / 32, 4), 256, SM_IP>>>(lb);
        k_convscan<<<B_ * 8, 800>>>(convW + l * INNER_ * 5, convb + l * INNER_,
                                    alp + l * INNER_, bet + l * INNER_,
                                    gam + l * INNER_, del + l * INNER_);
        k_outproj<<<M_ / 32, 256, SM_OP>>>(lb + 65536);
    }
    k_flatcvt<<<500, 256>>>(normf);
    k_final<<<dim3(CF_ / 128, KS_), 256>>>(outW);
    k_reduce<<<(B_ * CF_) / 256, 256>>>(outb, out);
}